// round 5
// baseline (speedup 1.0000x reference)
#include <cuda_runtime.h>
#include <cstdint>

#define NSP 4096      // H*W*D = 16^3
#define CCH 256
#define NHEADS 8
#define HD 32
#define QB 128
#define KB 64

// scratch (no cudaMalloc allowed)
__device__ float g_y[CCH * NSP];          // normalized conv output [C][N]
__device__ float g_qkv[3 * CCH * NSP];    // qkv [3C][N]
__device__ float g_att[CCH * NSP];        // attention output, channel-major [C][N]

// ---------------------------------------------------------------------------
__device__ __forceinline__ uint32_t f2tf32(float f) {
    uint32_t r; asm("cvt.rna.tf32.f32 %0, %1;" : "=r"(r) : "f"(f)); return r;
}
__device__ __forceinline__ uint32_t smem_u32(const void* p) {
    uint32_t a;
    asm("{ .reg .u64 t; cvta.to.shared.u64 t, %1; cvt.u32.u64 %0, t; }" : "=r"(a) : "l"(p));
    return a;
}
__device__ __forceinline__ void cp16(uint32_t saddr, const void* g) {
    asm volatile("cp.async.cg.shared.global [%0], [%1], 16;" :: "r"(saddr), "l"(g));
}
#define CP_COMMIT() asm volatile("cp.async.commit_group;" ::: "memory")
#define CP_WAIT0()  asm volatile("cp.async.wait_group 0;" ::: "memory")
#define CP_WAIT1()  asm volatile("cp.async.wait_group 1;" ::: "memory")

__device__ __forceinline__ void mma16n8k8(float c[4], const uint32_t a[4],
                                          uint32_t b0, uint32_t b1) {
    asm("mma.sync.aligned.m16n8k8.row.col.f32.tf32.tf32.f32 "
        "{%0,%1,%2,%3}, {%4,%5,%6,%7}, {%8,%9}, {%0,%1,%2,%3};"
        : "+f"(c[0]), "+f"(c[1]), "+f"(c[2]), "+f"(c[3])
        : "r"(a[0]), "r"(a[1]), "r"(a[2]), "r"(a[3]), "r"(b0), "r"(b1));
}

// fast exp2 (magic-number range reduction + degree-4 poly); valid |s| < 2^21
__device__ __forceinline__ float exp2m(float s, float& l) {
    float z = s + 12582912.0f;            // 1.5*2^23
    float f = s - (z - 12582912.0f);      // f in [-0.5, 0.5]
    int   e = __float_as_int(z) << 23;
    float p = 9.6181291e-3f;
    p = fmaf(p, f, 5.5504109e-2f);
    p = fmaf(p, f, 2.4022651e-1f);
    p = fmaf(p, f, 6.9314718e-1f);
    p = fmaf(p, f, 1.0f);
    float r = __int_as_float(__float_as_int(p) + e);
    l += r;
    return r;
}

// ---------------------------------------------------------------------------
// Kernel 1: depthwise 3x3x3 conv + bias + InstanceNorm (per channel).
// ---------------------------------------------------------------------------
__global__ __launch_bounds__(256) void conv_in_kernel(
    const float* __restrict__ x, const float* __restrict__ wdw,
    const float* __restrict__ bdw, float* __restrict__ y)
{
    const int c   = blockIdx.x;
    const int tid = threadIdx.x;
    __shared__ float xs[NSP];
    __shared__ float red[512];

    const float4* xg  = (const float4*)(x + (size_t)c * NSP);
    float4* xs4 = (float4*)xs;
    #pragma unroll
    for (int i = 0; i < 4; ++i) xs4[tid + 256 * i] = xg[tid + 256 * i];

    float wr[27];
    #pragma unroll
    for (int i = 0; i < 27; ++i) wr[i] = wdw[c * 27 + i];
    const float bias = bdw[c];
    __syncthreads();

    const int w  = tid >> 4;
    const int dd = tid & 15;

    float out[16];
    float s = 0.f, s2 = 0.f;
    for (int hh = 0; hh < 16; ++hh) {
        float acc = bias;
        #pragma unroll
        for (int i = 0; i < 3; ++i) {
            int ih = hh + i - 1;
            if ((unsigned)ih < 16u) {
                #pragma unroll
                for (int j = 0; j < 3; ++j) {
                    int iw = w + j - 1;
                    if ((unsigned)iw < 16u) {
                        #pragma unroll
                        for (int k = 0; k < 3; ++k) {
                            int id = dd + k - 1;
                            if ((unsigned)id < 16u)
                                acc = fmaf(xs[ih * 256 + iw * 16 + id], wr[i * 9 + j * 3 + k], acc);
                        }
                    }
                }
            }
        }
        out[hh] = acc;
        s += acc;
        s2 = fmaf(acc, acc, s2);
    }

    red[tid] = s; red[256 + tid] = s2;
    __syncthreads();
    for (int st = 128; st > 0; st >>= 1) {
        if (tid < st) { red[tid] += red[tid + st]; red[256 + tid] += red[256 + tid + st]; }
        __syncthreads();
    }
    const float mean = red[0] * (1.0f / NSP);
    const float var  = red[256] * (1.0f / NSP) - mean * mean;
    const float rs   = rsqrtf(var + 1e-5f);

    float* yc = y + (size_t)c * NSP;
    for (int hh = 0; hh < 16; ++hh)
        yc[hh * 256 + tid] = (out[hh] - mean) * rs;
}

// ---------------------------------------------------------------------------
// Kernel 2/4: tf32 mma.sync GEMM with row-bias, cp.async double-buffered.
// C[M,N] = A[M,K]·B[K,N] + bias[m].  BM=128, BN=64, BK=32, 4 warps.
// As [buf][m][k] stride 36 (frag reads bank-perfect), Bs [buf][k][n] stride 72.
// tf32 rounding at fragment read (ALU pipe).
// dyn smem: 2*128*36*4 + 2*32*72*4 = 55296 B.
// ---------------------------------------------------------------------------
__global__ __launch_bounds__(128) void gemm_tc(
    const float* __restrict__ A, const float* __restrict__ B,
    const float* __restrict__ bias, float* __restrict__ C,
    int M, int N, int K)
{
    extern __shared__ float gsm[];
    float (*As)[128][36] = (float(*)[128][36])gsm;            // 2 bufs
    float (*Bs)[32][72]  = (float(*)[32][72])(gsm + 2 * 128 * 36);

    const int tid  = threadIdx.x;
    const int w    = tid >> 5;
    const int lane = tid & 31;
    const int gid  = lane >> 2;
    const int tig  = lane & 3;
    const int bm   = blockIdx.y * 128;
    const int bn   = blockIdx.x * 64;

    const int am = tid >> 3;           // A row base (16 rows/pass)
    const int ak = (tid & 7) * 4;      // A k chunk
    const int bkk = tid >> 2;          // B k-row
    const int bnb = (tid & 3) * 16;    // B col base

    float acc[2][8][4] = {};

    // stage tile t into buffer b
    auto stage = [&](int b, int k0) {
        const float* ar = A + (size_t)(bm + am) * K + k0 + ak;
        #pragma unroll
        for (int p = 0; p < 8; ++p)
            cp16(smem_u32(&As[b][am + 16 * p][ak]), ar + (size_t)(16 * p) * K);
        const float* br = B + (size_t)(k0 + bkk) * N + bn + bnb;
        #pragma unroll
        for (int m2 = 0; m2 < 4; ++m2)
            cp16(smem_u32(&Bs[b][bkk][bnb + m2 * 4]), br + m2 * 4);
        CP_COMMIT();
    };

    const int NT = K / 32;
    stage(0, 0);

    for (int t = 0; t < NT; ++t) {
        if (t + 1 < NT) { stage((t + 1) & 1, (t + 1) * 32); CP_WAIT1(); }
        else            { CP_WAIT0(); }
        __syncthreads();

        const int b = t & 1;
        #pragma unroll
        for (int ks = 0; ks < 4; ++ks) {
            uint32_t a[2][4];
            #pragma unroll
            for (int u = 0; u < 2; ++u) {
                const int mb = w * 32 + u * 16 + gid;
                a[u][0] = f2tf32(As[b][mb][ks * 8 + tig]);
                a[u][1] = f2tf32(As[b][mb + 8][ks * 8 + tig]);
                a[u][2] = f2tf32(As[b][mb][ks * 8 + tig + 4]);
                a[u][3] = f2tf32(As[b][mb + 8][ks * 8 + tig + 4]);
            }
            #pragma unroll
            for (int nt = 0; nt < 8; ++nt) {
                uint32_t b0 = f2tf32(Bs[b][ks * 8 + tig][nt * 8 + gid]);
                uint32_t b1 = f2tf32(Bs[b][ks * 8 + tig + 4][nt * 8 + gid]);
                mma16n8k8(acc[0][nt], a[0], b0, b1);
                mma16n8k8(acc[1][nt], a[1], b0, b1);
            }
        }
        __syncthreads();
    }

    #pragma unroll
    for (int u = 0; u < 2; ++u) {
        const int m0 = bm + w * 32 + u * 16 + gid;
        const float bv0 = bias[m0];
        const float bv1 = bias[m0 + 8];
        #pragma unroll
        for (int nt = 0; nt < 8; ++nt) {
            const int n = bn + nt * 8 + tig * 2;
            float2 r0 = make_float2(acc[u][nt][0] + bv0, acc[u][nt][1] + bv0);
            float2 r1 = make_float2(acc[u][nt][2] + bv1, acc[u][nt][3] + bv1);
            *(float2*)(C + (size_t)m0 * N + n)       = r0;
            *(float2*)(C + (size_t)(m0 + 8) * N + n) = r1;
        }
    }
}

// ---------------------------------------------------------------------------
// Kernel 3: tf32 mma.sync flash attention, cp.async double-buffered K/V,
// QK-MMA fused with softmax per n-tile (S live range = 8 regs).
// grid (32, 8). 4 warps, 32 query rows/warp. K/V smem [buf][dim][key] str 72.
// dyn smem: 2*(2*32*72*4) + 4*32*68*4 = 36864 + 34816 = 71680 B.
// ---------------------------------------------------------------------------
__global__ __launch_bounds__(128) void attn_mma(
    const float* __restrict__ qkv, float* __restrict__ out)
{
    extern __shared__ float dsm[];
    float (*Ksm)[32][72] = (float(*)[32][72])dsm;
    float (*Vsm)[32][72] = (float(*)[32][72])(dsm + 2 * 32 * 72);
    float* Psm = dsm + 4 * 32 * 72;    // [4][32][68]

    const int tid  = threadIdx.x;
    const int w    = tid >> 5;
    const int lane = tid & 31;
    const int gid  = lane >> 2;
    const int tig  = lane & 3;
    const int h    = blockIdx.y;
    const int n0   = blockIdx.x * QB;

    const float SC = 0.17677669529663688f * 1.4426950408889634f; // hd^-0.5 * log2e

    const float* qb = qkv + (size_t)(h * HD) * NSP;
    const float* kb = qkv + (size_t)(CCH + h * HD) * NSP;
    const float* vb = qkv + (size_t)(2 * CCH + h * HD) * NSP;

    const int ld = tid >> 2;            // dim row 0..31
    const int lk = (tid & 3) * 16;      // key col base

    auto stage = [&](int b, int j0) {
        #pragma unroll
        for (int m = 0; m < 4; ++m) {
            cp16(smem_u32(&Ksm[b][ld][lk + m * 4]), kb + (size_t)ld * NSP + j0 + lk + m * 4);
            cp16(smem_u32(&Vsm[b][ld][lk + m * 4]), vb + (size_t)ld * NSP + j0 + lk + m * 4);
        }
        CP_COMMIT();
    };

    stage(0, 0);   // overlap with Q fragment loads below

    uint32_t qa[2][4][4];
    #pragma unroll
    for (int u = 0; u < 2; ++u) {
        const int rl = n0 + w * 32 + u * 16 + gid;
        #pragma unroll
        for (int ks = 0; ks < 4; ++ks) {
            const int d0 = ks * 8 + tig;
            qa[u][ks][0] = f2tf32(qb[d0 * NSP + rl] * SC);
            qa[u][ks][1] = f2tf32(qb[d0 * NSP + rl + 8] * SC);
            qa[u][ks][2] = f2tf32(qb[(d0 + 4) * NSP + rl] * SC);
            qa[u][ks][3] = f2tf32(qb[(d0 + 4) * NSP + rl + 8] * SC);
        }
    }

    float o[2][4][4] = {};
    float l[2][2] = {};
    float* Pw = Psm + w * 32 * 68;

    const int NT = NSP / KB;   // 64 tiles
    for (int t = 0; t < NT; ++t) {
        if (t + 1 < NT) { stage((t + 1) & 1, (t + 1) * KB); CP_WAIT1(); }
        else            { CP_WAIT0(); }
        __syncthreads();
        const int b = t & 1;

        // S = Q@K^T fused with softmax, per n-tile
        #pragma unroll
        for (int nt = 0; nt < 8; ++nt) {
            float s0[4] = {}, s1[4] = {};
            #pragma unroll
            for (int ks = 0; ks < 4; ++ks) {
                uint32_t b0 = f2tf32(Ksm[b][ks * 8 + tig][nt * 8 + gid]);
                uint32_t b1 = f2tf32(Ksm[b][ks * 8 + tig + 4][nt * 8 + gid]);
                mma16n8k8(s0, qa[0][ks], b0, b1);
                mma16n8k8(s1, qa[1][ks], b0, b1);
            }
            const int cb = nt * 8 + 2 * tig;
            {
                float p0 = exp2m(s0[0], l[0][0]);
                float p1 = exp2m(s0[1], l[0][0]);
                float p2 = exp2m(s0[2], l[0][1]);
                float p3 = exp2m(s0[3], l[0][1]);
                Pw[gid * 68 + cb]           = __uint_as_float(f2tf32(p0));
                Pw[gid * 68 + cb + 1]       = __uint_as_float(f2tf32(p1));
                Pw[(gid + 8) * 68 + cb]     = __uint_as_float(f2tf32(p2));
                Pw[(gid + 8) * 68 + cb + 1] = __uint_as_float(f2tf32(p3));
            }
            {
                float p0 = exp2m(s1[0], l[1][0]);
                float p1 = exp2m(s1[1], l[1][0]);
                float p2 = exp2m(s1[2], l[1][1]);
                float p3 = exp2m(s1[3], l[1][1]);
                Pw[(16 + gid) * 68 + cb]     = __uint_as_float(f2tf32(p0));
                Pw[(16 + gid) * 68 + cb + 1] = __uint_as_float(f2tf32(p1));
                Pw[(24 + gid) * 68 + cb]     = __uint_as_float(f2tf32(p2));
                Pw[(24 + gid) * 68 + cb + 1] = __uint_as_float(f2tf32(p3));
            }
        }
        __syncwarp();

        // O += P @ V
        #pragma unroll
        for (int ks = 0; ks < 8; ++ks) {
            uint32_t a0[4], a1[4];
            const int kc = ks * 8 + tig;
            a0[0] = __float_as_uint(Pw[gid * 68 + kc]);
            a0[1] = __float_as_uint(Pw[(gid + 8) * 68 + kc]);
            a0[2] = __float_as_uint(Pw[gid * 68 + kc + 4]);
            a0[3] = __float_as_uint(Pw[(gid + 8) * 68 + kc + 4]);
            a1[0] = __float_as_uint(Pw[(16 + gid) * 68 + kc]);
            a1[1] = __float_as_uint(Pw[(24 + gid) * 68 + kc]);
            a1[2] = __float_as_uint(Pw[(16 + gid) * 68 + kc + 4]);
            a1[3] = __float_as_uint(Pw[(24 + gid) * 68 + kc + 4]);
            #pragma unroll
            for (int nt = 0; nt < 4; ++nt) {
                uint32_t b0 = f2tf32(Vsm[b][nt * 8 + gid][ks * 8 + tig]);
                uint32_t b1 = f2tf32(Vsm[b][nt * 8 + gid][ks * 8 + tig + 4]);
                mma16n8k8(o[0][nt], a0, b0, b1);
                mma16n8k8(o[1][nt], a1, b0, b1);
            }
        }
        __syncthreads();
    }

    #pragma unroll
    for (int u = 0; u < 2; ++u)
        #pragma unroll
        for (int v = 0; v < 2; ++v) {
            l[u][v] += __shfl_xor_sync(0xFFFFFFFFu, l[u][v], 1);
            l[u][v] += __shfl_xor_sync(0xFFFFFFFFu, l[u][v], 2);
        }
    const float il[2][2] = { {1.f / l[0][0], 1.f / l[0][1]},
                             {1.f / l[1][0], 1.f / l[1][1]} };

    __syncthreads();
    #pragma unroll
    for (int u = 0; u < 2; ++u)
        #pragma unroll
        for (int nt = 0; nt < 4; ++nt) {
            const int cb = nt * 8 + 2 * tig;
            Pw[(u * 16 + gid) * 68 + cb]         = o[u][nt][0] * il[u][0];
            Pw[(u * 16 + gid) * 68 + cb + 1]     = o[u][nt][1] * il[u][0];
            Pw[(u * 16 + gid + 8) * 68 + cb]     = o[u][nt][2] * il[u][1];
            Pw[(u * 16 + gid + 8) * 68 + cb + 1] = o[u][nt][3] * il[u][1];
        }
    __syncthreads();

    const float* Pr = Psm + (tid >> 5) * 32 * 68 + (tid & 31) * 68;
    float* ob = out + (size_t)(h * HD) * NSP + n0 + tid;
    #pragma unroll
    for (int d = 0; d < 32; ++d)
        ob[(size_t)d * NSP] = Pr[d];
}

// ---------------------------------------------------------------------------
extern "C" void kernel_launch(void* const* d_in, const int* in_sizes, int n_in,
                              void* d_out, int out_size)
{
    const float* x      = (const float*)d_in[0];
    const float* w_dw   = (const float*)d_in[1];
    const float* b_dw   = (const float*)d_in[2];
    const float* w_qkv  = (const float*)d_in[3];
    const float* b_qkv  = (const float*)d_in[4];
    const float* w_proj = (const float*)d_in[5];
    const float* b_proj = (const float*)d_in[6];
    float* outp = (float*)d_out;

    float *py, *pqkv, *patt;
    cudaGetSymbolAddress((void**)&py,   g_y);
    cudaGetSymbolAddress((void**)&pqkv, g_qkv);
    cudaGetSymbolAddress((void**)&patt, g_att);

    const int GEMM_SMEM = (2 * 128 * 36 + 2 * 32 * 72) * 4;   // 55296 B
    const int ATTN_SMEM = (4 * 32 * 72 + 4 * 32 * 68) * 4;    // 71680 B
    static int smem_set = 0;
    if (!smem_set) {
        cudaFuncSetAttribute(gemm_tc,  cudaFuncAttributeMaxDynamicSharedMemorySize, GEMM_SMEM);
        cudaFuncSetAttribute(attn_mma, cudaFuncAttributeMaxDynamicSharedMemorySize, ATTN_SMEM);
        smem_set = 1;
    }

    conv_in_kernel<<<CCH, 256>>>(x, w_dw, b_dw, py);
    gemm_tc<<<dim3(NSP / 64, (3 * CCH) / 128), 128, GEMM_SMEM>>>(w_qkv, py, b_qkv, pqkv, 3 * CCH, NSP, CCH);
    attn_mma<<<dim3(NSP / QB, NHEADS), 128, ATTN_SMEM>>>(pqkv, patt);
    gemm_tc<<<dim3(NSP / 64, CCH / 128), 128, GEMM_SMEM>>>(w_proj, patt, b_proj, outp, CCH, NSP, CCH);
}

// round 6
// speedup vs baseline: 1.0967x; 1.0967x over previous
#include <cuda_runtime.h>
#include <cstdint>

#define NSP 4096      // H*W*D = 16^3
#define CCH 256
#define NHEADS 8
#define HD 32
#define QB 256
#define KB 64

// scratch (no cudaMalloc allowed)
__device__ float g_y[CCH * NSP];          // normalized conv output [C][N]
__device__ float g_qkv[3 * CCH * NSP];    // qkv [3C][N]
__device__ float g_att[CCH * NSP];        // attention output, channel-major [C][N]

// ---------------------------------------------------------------------------
__device__ __forceinline__ uint32_t f2tf32(float f) {
    uint32_t r; asm("cvt.rna.tf32.f32 %0, %1;" : "=r"(r) : "f"(f)); return r;
}
__device__ __forceinline__ uint32_t smem_u32(const void* p) {
    uint32_t a;
    asm("{ .reg .u64 t; cvta.to.shared.u64 t, %1; cvt.u32.u64 %0, t; }" : "=r"(a) : "l"(p));
    return a;
}
__device__ __forceinline__ void cp16(uint32_t saddr, const void* g) {
    asm volatile("cp.async.cg.shared.global [%0], [%1], 16;" :: "r"(saddr), "l"(g));
}
#define CP_COMMIT() asm volatile("cp.async.commit_group;" ::: "memory")
#define CP_WAIT0()  asm volatile("cp.async.wait_group 0;" ::: "memory")
#define CP_WAIT1()  asm volatile("cp.async.wait_group 1;" ::: "memory")

__device__ __forceinline__ void mma16n8k8(float c[4], const uint32_t a[4],
                                          uint32_t b0, uint32_t b1) {
    asm("mma.sync.aligned.m16n8k8.row.col.f32.tf32.tf32.f32 "
        "{%0,%1,%2,%3}, {%4,%5,%6,%7}, {%8,%9}, {%0,%1,%2,%3};"
        : "+f"(c[0]), "+f"(c[1]), "+f"(c[2]), "+f"(c[3])
        : "r"(a[0]), "r"(a[1]), "r"(a[2]), "r"(a[3]), "r"(b0), "r"(b1));
}

// fast exp2 (magic-number range reduction + degree-4 poly); valid |s| < 2^21
__device__ __forceinline__ float exp2m(float s, float& l) {
    float z = s + 12582912.0f;            // 1.5*2^23
    float f = s - (z - 12582912.0f);      // f in [-0.5, 0.5]
    int   e = __float_as_int(z) << 23;
    float p = 9.6181291e-3f;
    p = fmaf(p, f, 5.5504109e-2f);
    p = fmaf(p, f, 2.4022651e-1f);
    p = fmaf(p, f, 6.9314718e-1f);
    p = fmaf(p, f, 1.0f);
    float r = __int_as_float(__float_as_int(p) + e);
    l += r;
    return r;
}

// ---------------------------------------------------------------------------
// Kernel 1: depthwise 3x3x3 conv + bias + InstanceNorm (per channel).
// ---------------------------------------------------------------------------
__global__ __launch_bounds__(256) void conv_in_kernel(
    const float* __restrict__ x, const float* __restrict__ wdw,
    const float* __restrict__ bdw, float* __restrict__ y)
{
    const int c   = blockIdx.x;
    const int tid = threadIdx.x;
    __shared__ float xs[NSP];
    __shared__ float red[512];

    const float4* xg  = (const float4*)(x + (size_t)c * NSP);
    float4* xs4 = (float4*)xs;
    #pragma unroll
    for (int i = 0; i < 4; ++i) xs4[tid + 256 * i] = xg[tid + 256 * i];

    float wr[27];
    #pragma unroll
    for (int i = 0; i < 27; ++i) wr[i] = wdw[c * 27 + i];
    const float bias = bdw[c];
    __syncthreads();

    const int w  = tid >> 4;
    const int dd = tid & 15;

    float out[16];
    float s = 0.f, s2 = 0.f;
    for (int hh = 0; hh < 16; ++hh) {
        float acc = bias;
        #pragma unroll
        for (int i = 0; i < 3; ++i) {
            int ih = hh + i - 1;
            if ((unsigned)ih < 16u) {
                #pragma unroll
                for (int j = 0; j < 3; ++j) {
                    int iw = w + j - 1;
                    if ((unsigned)iw < 16u) {
                        #pragma unroll
                        for (int k = 0; k < 3; ++k) {
                            int id = dd + k - 1;
                            if ((unsigned)id < 16u)
                                acc = fmaf(xs[ih * 256 + iw * 16 + id], wr[i * 9 + j * 3 + k], acc);
                        }
                    }
                }
            }
        }
        out[hh] = acc;
        s += acc;
        s2 = fmaf(acc, acc, s2);
    }

    red[tid] = s; red[256 + tid] = s2;
    __syncthreads();
    for (int st = 128; st > 0; st >>= 1) {
        if (tid < st) { red[tid] += red[tid + st]; red[256 + tid] += red[256 + tid + st]; }
        __syncthreads();
    }
    const float mean = red[0] * (1.0f / NSP);
    const float var  = red[256] * (1.0f / NSP) - mean * mean;
    const float rs   = rsqrtf(var + 1e-5f);

    float* yc = y + (size_t)c * NSP;
    for (int hh = 0; hh < 16; ++hh)
        yc[hh * 256 + tid] = (out[hh] - mean) * rs;
}

// ---------------------------------------------------------------------------
// Kernel 2/4: tf32 mma.sync GEMM with row-bias, cp.async double-buffered.
// C[M,N] = A[M,K]·B[K,N] + bias[m].  BM=128, BN=128, BK=32, 8 warps (4m x 2n).
// As [buf][128][36], Bs [buf][32][136]. tf32 rounding at fragment read.
// dyn smem: (2*128*36 + 2*32*136)*4 = 71680 B.
// ---------------------------------------------------------------------------
__global__ __launch_bounds__(256) void gemm_tc(
    const float* __restrict__ A, const float* __restrict__ B,
    const float* __restrict__ bias, float* __restrict__ C,
    int M, int N, int K)
{
    extern __shared__ float gsm[];
    float (*As)[128][36]  = (float(*)[128][36])gsm;
    float (*Bs)[32][136]  = (float(*)[32][136])(gsm + 2 * 128 * 36);

    const int tid  = threadIdx.x;
    const int w    = tid >> 5;
    const int lane = tid & 31;
    const int gid  = lane >> 2;
    const int tig  = lane & 3;
    const int wm   = w >> 1;           // m-group 0..3
    const int wn   = w & 1;            // n-half 0..1
    const int bm   = blockIdx.y * 128;
    const int bn   = blockIdx.x * 128;

    const int am  = tid >> 1;          // A row (0..127), 2 threads/row
    const int ak  = (tid & 1) * 16;    // A k half
    const int bkk = tid >> 3;          // B k-row (0..31)
    const int bnb = (tid & 7) * 16;    // B col base

    float acc[2][8][4] = {};

    auto stage = [&](int b, int k0) {
        const float* ar = A + (size_t)(bm + am) * K + k0 + ak;
        #pragma unroll
        for (int p = 0; p < 4; ++p)
            cp16(smem_u32(&As[b][am][ak + p * 4]), ar + p * 4);
        const float* br = B + (size_t)(k0 + bkk) * N + bn + bnb;
        #pragma unroll
        for (int p = 0; p < 4; ++p)
            cp16(smem_u32(&Bs[b][bkk][bnb + p * 4]), br + p * 4);
        CP_COMMIT();
    };

    const int NT = K / 32;
    stage(0, 0);

    for (int t = 0; t < NT; ++t) {
        if (t + 1 < NT) { stage((t + 1) & 1, (t + 1) * 32); CP_WAIT1(); }
        else            { CP_WAIT0(); }
        __syncthreads();

        const int b = t & 1;
        #pragma unroll
        for (int ks = 0; ks < 4; ++ks) {
            uint32_t a[2][4];
            #pragma unroll
            for (int u = 0; u < 2; ++u) {
                const int mb = wm * 32 + u * 16 + gid;
                a[u][0] = f2tf32(As[b][mb][ks * 8 + tig]);
                a[u][1] = f2tf32(As[b][mb + 8][ks * 8 + tig]);
                a[u][2] = f2tf32(As[b][mb][ks * 8 + tig + 4]);
                a[u][3] = f2tf32(As[b][mb + 8][ks * 8 + tig + 4]);
            }
            #pragma unroll
            for (int nt = 0; nt < 8; ++nt) {
                uint32_t b0 = f2tf32(Bs[b][ks * 8 + tig][wn * 64 + nt * 8 + gid]);
                uint32_t b1 = f2tf32(Bs[b][ks * 8 + tig + 4][wn * 64 + nt * 8 + gid]);
                mma16n8k8(acc[0][nt], a[0], b0, b1);
                mma16n8k8(acc[1][nt], a[1], b0, b1);
            }
        }
        __syncthreads();
    }

    #pragma unroll
    for (int u = 0; u < 2; ++u) {
        const int m0 = bm + wm * 32 + u * 16 + gid;
        const float bv0 = bias[m0];
        const float bv1 = bias[m0 + 8];
        #pragma unroll
        for (int nt = 0; nt < 8; ++nt) {
            const int n = bn + wn * 64 + nt * 8 + tig * 2;
            float2 r0 = make_float2(acc[u][nt][0] + bv0, acc[u][nt][1] + bv0);
            float2 r1 = make_float2(acc[u][nt][2] + bv1, acc[u][nt][3] + bv1);
            *(float2*)(C + (size_t)m0 * N + n)       = r0;
            *(float2*)(C + (size_t)(m0 + 8) * N + n) = r1;
        }
    }
}

// ---------------------------------------------------------------------------
// Kernel 3: tf32 mma.sync flash attention, cp.async double-buffered K/V.
// QB=256, 8 warps (32 query rows/warp), grid (16, 8) = 128 CTAs = 1 wave.
// K/V smem [buf][dim][key] stride 72; P per-warp [32][68].
// dyn smem: (2*2*32*72 + 8*32*68)*4 = 106496 B.
// ---------------------------------------------------------------------------
__global__ __launch_bounds__(256) void attn_mma(
    const float* __restrict__ qkv, float* __restrict__ out)
{
    extern __shared__ float dsm[];
    float (*Ksm)[32][72] = (float(*)[32][72])dsm;
    float (*Vsm)[32][72] = (float(*)[32][72])(dsm + 2 * 32 * 72);
    float* Psm = dsm + 4 * 32 * 72;    // [8][32][68]

    const int tid  = threadIdx.x;
    const int w    = tid >> 5;
    const int lane = tid & 31;
    const int gid  = lane >> 2;
    const int tig  = lane & 3;
    const int h    = blockIdx.y;
    const int n0   = blockIdx.x * QB;

    const float SC = 0.17677669529663688f * 1.4426950408889634f; // hd^-0.5 * log2e

    const float* qb = qkv + (size_t)(h * HD) * NSP;
    const float* kb = qkv + (size_t)(CCH + h * HD) * NSP;
    const float* vb = qkv + (size_t)(2 * CCH + h * HD) * NSP;

    const int ld = tid >> 3;            // dim row 0..31
    const int lk = (tid & 7) * 8;       // key col base (8 cols = 2 float4)

    auto stage = [&](int b, int j0) {
        #pragma unroll
        for (int m = 0; m < 2; ++m) {
            cp16(smem_u32(&Ksm[b][ld][lk + m * 4]), kb + (size_t)ld * NSP + j0 + lk + m * 4);
            cp16(smem_u32(&Vsm[b][ld][lk + m * 4]), vb + (size_t)ld * NSP + j0 + lk + m * 4);
        }
        CP_COMMIT();
    };

    stage(0, 0);   // overlap with Q fragment loads below

    uint32_t qa[2][4][4];
    #pragma unroll
    for (int u = 0; u < 2; ++u) {
        const int rl = n0 + w * 32 + u * 16 + gid;
        #pragma unroll
        for (int ks = 0; ks < 4; ++ks) {
            const int d0 = ks * 8 + tig;
            qa[u][ks][0] = f2tf32(qb[d0 * NSP + rl] * SC);
            qa[u][ks][1] = f2tf32(qb[d0 * NSP + rl + 8] * SC);
            qa[u][ks][2] = f2tf32(qb[(d0 + 4) * NSP + rl] * SC);
            qa[u][ks][3] = f2tf32(qb[(d0 + 4) * NSP + rl + 8] * SC);
        }
    }

    float o[2][4][4] = {};
    float l[2][2] = {};
    float* Pw = Psm + w * 32 * 68;

    const int NT = NSP / KB;   // 64 tiles
    for (int t = 0; t < NT; ++t) {
        if (t + 1 < NT) { stage((t + 1) & 1, (t + 1) * KB); CP_WAIT1(); }
        else            { CP_WAIT0(); }
        __syncthreads();
        const int b = t & 1;

        // S = Q@K^T fused with softmax, per n-tile
        #pragma unroll
        for (int nt = 0; nt < 8; ++nt) {
            float s0[4] = {}, s1[4] = {};
            #pragma unroll
            for (int ks = 0; ks < 4; ++ks) {
                uint32_t b0 = f2tf32(Ksm[b][ks * 8 + tig][nt * 8 + gid]);
                uint32_t b1 = f2tf32(Ksm[b][ks * 8 + tig + 4][nt * 8 + gid]);
                mma16n8k8(s0, qa[0][ks], b0, b1);
                mma16n8k8(s1, qa[1][ks], b0, b1);
            }
            const int cb = nt * 8 + 2 * tig;
            {
                float p0 = exp2m(s0[0], l[0][0]);
                float p1 = exp2m(s0[1], l[0][0]);
                float p2 = exp2m(s0[2], l[0][1]);
                float p3 = exp2m(s0[3], l[0][1]);
                Pw[gid * 68 + cb]           = __uint_as_float(f2tf32(p0));
                Pw[gid * 68 + cb + 1]       = __uint_as_float(f2tf32(p1));
                Pw[(gid + 8) * 68 + cb]     = __uint_as_float(f2tf32(p2));
                Pw[(gid + 8) * 68 + cb + 1] = __uint_as_float(f2tf32(p3));
            }
            {
                float p0 = exp2m(s1[0], l[1][0]);
                float p1 = exp2m(s1[1], l[1][0]);
                float p2 = exp2m(s1[2], l[1][1]);
                float p3 = exp2m(s1[3], l[1][1]);
                Pw[(16 + gid) * 68 + cb]     = __uint_as_float(f2tf32(p0));
                Pw[(16 + gid) * 68 + cb + 1] = __uint_as_float(f2tf32(p1));
                Pw[(24 + gid) * 68 + cb]     = __uint_as_float(f2tf32(p2));
                Pw[(24 + gid) * 68 + cb + 1] = __uint_as_float(f2tf32(p3));
            }
        }
        __syncwarp();

        // O += P @ V
        #pragma unroll
        for (int ks = 0; ks < 8; ++ks) {
            uint32_t a0[4], a1[4];
            const int kc = ks * 8 + tig;
            a0[0] = __float_as_uint(Pw[gid * 68 + kc]);
            a0[1] = __float_as_uint(Pw[(gid + 8) * 68 + kc]);
            a0[2] = __float_as_uint(Pw[gid * 68 + kc + 4]);
            a0[3] = __float_as_uint(Pw[(gid + 8) * 68 + kc + 4]);
            a1[0] = __float_as_uint(Pw[(16 + gid) * 68 + kc]);
            a1[1] = __float_as_uint(Pw[(24 + gid) * 68 + kc]);
            a1[2] = __float_as_uint(Pw[(16 + gid) * 68 + kc + 4]);
            a1[3] = __float_as_uint(Pw[(24 + gid) * 68 + kc + 4]);
            #pragma unroll
            for (int nt = 0; nt < 4; ++nt) {
                uint32_t b0 = f2tf32(Vsm[b][nt * 8 + gid][ks * 8 + tig]);
                uint32_t b1 = f2tf32(Vsm[b][nt * 8 + gid][ks * 8 + tig + 4]);
                mma16n8k8(o[0][nt], a0, b0, b1);
                mma16n8k8(o[1][nt], a1, b0, b1);
            }
        }
        __syncthreads();
    }

    #pragma unroll
    for (int u = 0; u < 2; ++u)
        #pragma unroll
        for (int v = 0; v < 2; ++v) {
            l[u][v] += __shfl_xor_sync(0xFFFFFFFFu, l[u][v], 1);
            l[u][v] += __shfl_xor_sync(0xFFFFFFFFu, l[u][v], 2);
        }
    const float il[2][2] = { {1.f / l[0][0], 1.f / l[0][1]},
                             {1.f / l[1][0], 1.f / l[1][1]} };

    __syncthreads();
    #pragma unroll
    for (int u = 0; u < 2; ++u)
        #pragma unroll
        for (int nt = 0; nt < 4; ++nt) {
            const int cb = nt * 8 + 2 * tig;
            Pw[(u * 16 + gid) * 68 + cb]         = o[u][nt][0] * il[u][0];
            Pw[(u * 16 + gid) * 68 + cb + 1]     = o[u][nt][1] * il[u][0];
            Pw[(u * 16 + gid + 8) * 68 + cb]     = o[u][nt][2] * il[u][1];
            Pw[(u * 16 + gid + 8) * 68 + cb + 1] = o[u][nt][3] * il[u][1];
        }
    __syncthreads();

    const float* Pr = Psm + (tid >> 5) * 32 * 68 + (tid & 31) * 68;
    float* ob = out + (size_t)(h * HD) * NSP + n0 + tid;
    #pragma unroll
    for (int d = 0; d < 32; ++d)
        ob[(size_t)d * NSP] = Pr[d];
}

// ---------------------------------------------------------------------------
extern "C" void kernel_launch(void* const* d_in, const int* in_sizes, int n_in,
                              void* d_out, int out_size)
{
    const float* x      = (const float*)d_in[0];
    const float* w_dw   = (const float*)d_in[1];
    const float* b_dw   = (const float*)d_in[2];
    const float* w_qkv  = (const float*)d_in[3];
    const float* b_qkv  = (const float*)d_in[4];
    const float* w_proj = (const float*)d_in[5];
    const float* b_proj = (const float*)d_in[6];
    float* outp = (float*)d_out;

    float *py, *pqkv, *patt;
    cudaGetSymbolAddress((void**)&py,   g_y);
    cudaGetSymbolAddress((void**)&pqkv, g_qkv);
    cudaGetSymbolAddress((void**)&patt, g_att);

    const int GEMM_SMEM = (2 * 128 * 36 + 2 * 32 * 136) * 4;  // 71680 B
    const int ATTN_SMEM = (4 * 32 * 72 + 8 * 32 * 68) * 4;    // 106496 B
    static int smem_set = 0;
    if (!smem_set) {
        cudaFuncSetAttribute(gemm_tc,  cudaFuncAttributeMaxDynamicSharedMemorySize, GEMM_SMEM);
        cudaFuncSetAttribute(attn_mma, cudaFuncAttributeMaxDynamicSharedMemorySize, ATTN_SMEM);
        smem_set = 1;
    }

    conv_in_kernel<<<CCH, 256>>>(x, w_dw, b_dw, py);
    gemm_tc<<<dim3(NSP / 128, (3 * CCH) / 128), 256, GEMM_SMEM>>>(w_qkv, py, b_qkv, pqkv, 3 * CCH, NSP, CCH);
    attn_mma<<<dim3(NSP / QB, NHEADS), 256, ATTN_SMEM>>>(pqkv, patt);
    gemm_tc<<<dim3(NSP / 128, CCH / 128), 256, GEMM_SMEM>>>(w_proj, patt, b_proj, outp, CCH, NSP, CCH);
}

// round 7
// speedup vs baseline: 1.9360x; 1.7652x over previous
#include <cuda_runtime.h>
#include <cuda_fp16.h>
#include <cstdint>

#define NSP 4096      // H*W*D = 16^3
#define CCH 256
#define NHEADS 8
#define HD 32
#define QB 256
#define KB 64

// scratch (no cudaMalloc allowed)
__device__ float g_y[CCH * NSP];          // normalized conv output [C][N]
__device__ float g_qkv[3 * CCH * NSP];    // qkv [3C][N]
__device__ float g_att[CCH * NSP];        // attention output, channel-major [C][N]

// ---------------------------------------------------------------------------
__device__ __forceinline__ uint32_t f2tf32(float f) {
    uint32_t r; asm("cvt.rna.tf32.f32 %0, %1;" : "=r"(r) : "f"(f)); return r;
}
__device__ __forceinline__ uint32_t smem_u32(const void* p) {
    uint32_t a;
    asm("{ .reg .u64 t; cvta.to.shared.u64 t, %1; cvt.u32.u64 %0, t; }" : "=r"(a) : "l"(p));
    return a;
}
__device__ __forceinline__ void cp16(uint32_t saddr, const void* g) {
    asm volatile("cp.async.cg.shared.global [%0], [%1], 16;" :: "r"(saddr), "l"(g));
}
#define CP_COMMIT() asm volatile("cp.async.commit_group;" ::: "memory")
#define CP_WAIT0()  asm volatile("cp.async.wait_group 0;" ::: "memory")
#define CP_WAIT1()  asm volatile("cp.async.wait_group 1;" ::: "memory")

__device__ __forceinline__ void mma16n8k8(float c[4], const uint32_t a[4],
                                          uint32_t b0, uint32_t b1) {
    asm("mma.sync.aligned.m16n8k8.row.col.f32.tf32.tf32.f32 "
        "{%0,%1,%2,%3}, {%4,%5,%6,%7}, {%8,%9}, {%0,%1,%2,%3};"
        : "+f"(c[0]), "+f"(c[1]), "+f"(c[2]), "+f"(c[3])
        : "r"(a[0]), "r"(a[1]), "r"(a[2]), "r"(a[3]), "r"(b0), "r"(b1));
}
__device__ __forceinline__ void mmaf16(float c[4], const uint32_t a[4],
                                       uint32_t b0, uint32_t b1) {
    asm("mma.sync.aligned.m16n8k16.row.col.f32.f16.f16.f32 "
        "{%0,%1,%2,%3}, {%4,%5,%6,%7}, {%8,%9}, {%0,%1,%2,%3};"
        : "+f"(c[0]), "+f"(c[1]), "+f"(c[2]), "+f"(c[3])
        : "r"(a[0]), "r"(a[1]), "r"(a[2]), "r"(a[3]), "r"(b0), "r"(b1));
}
__device__ __forceinline__ uint32_t packh2(float lo, float hi) {
    __half2 h = __float22half2_rn(make_float2(lo, hi));
    return *reinterpret_cast<uint32_t*>(&h);
}
__device__ __forceinline__ float ex2(float s) {
    float r; asm("ex2.approx.f32 %0, %1;" : "=f"(r) : "f"(s)); return r;
}

// ---------------------------------------------------------------------------
// Kernel 1: depthwise 3x3x3 conv + bias + InstanceNorm (per channel).
// ---------------------------------------------------------------------------
__global__ __launch_bounds__(256) void conv_in_kernel(
    const float* __restrict__ x, const float* __restrict__ wdw,
    const float* __restrict__ bdw, float* __restrict__ y)
{
    const int c   = blockIdx.x;
    const int tid = threadIdx.x;
    __shared__ float xs[NSP];
    __shared__ float red[512];

    const float4* xg  = (const float4*)(x + (size_t)c * NSP);
    float4* xs4 = (float4*)xs;
    #pragma unroll
    for (int i = 0; i < 4; ++i) xs4[tid + 256 * i] = xg[tid + 256 * i];

    float wr[27];
    #pragma unroll
    for (int i = 0; i < 27; ++i) wr[i] = wdw[c * 27 + i];
    const float bias = bdw[c];
    __syncthreads();

    const int w  = tid >> 4;
    const int dd = tid & 15;

    float out[16];
    float s = 0.f, s2 = 0.f;
    for (int hh = 0; hh < 16; ++hh) {
        float acc = bias;
        #pragma unroll
        for (int i = 0; i < 3; ++i) {
            int ih = hh + i - 1;
            if ((unsigned)ih < 16u) {
                #pragma unroll
                for (int j = 0; j < 3; ++j) {
                    int iw = w + j - 1;
                    if ((unsigned)iw < 16u) {
                        #pragma unroll
                        for (int k = 0; k < 3; ++k) {
                            int id = dd + k - 1;
                            if ((unsigned)id < 16u)
                                acc = fmaf(xs[ih * 256 + iw * 16 + id], wr[i * 9 + j * 3 + k], acc);
                        }
                    }
                }
            }
        }
        out[hh] = acc;
        s += acc;
        s2 = fmaf(acc, acc, s2);
    }

    red[tid] = s; red[256 + tid] = s2;
    __syncthreads();
    for (int st = 128; st > 0; st >>= 1) {
        if (tid < st) { red[tid] += red[tid + st]; red[256 + tid] += red[256 + tid + st]; }
        __syncthreads();
    }
    const float mean = red[0] * (1.0f / NSP);
    const float var  = red[256] * (1.0f / NSP) - mean * mean;
    const float rs   = rsqrtf(var + 1e-5f);

    float* yc = y + (size_t)c * NSP;
    for (int hh = 0; hh < 16; ++hh)
        yc[hh * 256 + tid] = (out[hh] - mean) * rs;
}

// ---------------------------------------------------------------------------
// Kernel 2/4: tf32 mma.sync GEMM with row-bias, cp.async double-buffered.
// Templated BN (64 or 128). BM=128, BK=32, 8 warps (4m x 2n halves of BN).
// ---------------------------------------------------------------------------
template<int BN>
__global__ __launch_bounds__(256) void gemm_tc(
    const float* __restrict__ A, const float* __restrict__ B,
    const float* __restrict__ bias, float* __restrict__ C,
    int M, int N, int K)
{
    constexpr int BSTR = BN + 8;
    constexpr int NTW  = BN / 16;        // n-tiles per warp
    extern __shared__ float gsm[];
    float (*As)[128][36]   = (float(*)[128][36])gsm;
    float (*Bs)[32][BSTR]  = (float(*)[32][BSTR])(gsm + 2 * 128 * 36);

    const int tid  = threadIdx.x;
    const int w    = tid >> 5;
    const int lane = tid & 31;
    const int gid  = lane >> 2;
    const int tig  = lane & 3;
    const int wm   = w >> 1;
    const int wn   = w & 1;
    const int bm   = blockIdx.y * 128;
    const int bn   = blockIdx.x * BN;

    const int am  = tid >> 1;
    const int ak  = (tid & 1) * 16;
    const int bkk = tid >> 3;
    const int bnb = (tid & 7) * (BN / 8);

    float acc[2][NTW][4] = {};

    auto stage = [&](int b, int k0) {
        const float* ar = A + (size_t)(bm + am) * K + k0 + ak;
        #pragma unroll
        for (int p = 0; p < 4; ++p)
            cp16(smem_u32(&As[b][am][ak + p * 4]), ar + p * 4);
        const float* br = B + (size_t)(k0 + bkk) * N + bn + bnb;
        #pragma unroll
        for (int p = 0; p < BN / 32; ++p)
            cp16(smem_u32(&Bs[b][bkk][bnb + p * 4]), br + p * 4);
        CP_COMMIT();
    };

    const int NT = K / 32;
    stage(0, 0);

    for (int t = 0; t < NT; ++t) {
        if (t + 1 < NT) { stage((t + 1) & 1, (t + 1) * 32); CP_WAIT1(); }
        else            { CP_WAIT0(); }
        __syncthreads();

        const int b = t & 1;
        #pragma unroll
        for (int ks = 0; ks < 4; ++ks) {
            uint32_t a[2][4];
            #pragma unroll
            for (int u = 0; u < 2; ++u) {
                const int mb = wm * 32 + u * 16 + gid;
                a[u][0] = f2tf32(As[b][mb][ks * 8 + tig]);
                a[u][1] = f2tf32(As[b][mb + 8][ks * 8 + tig]);
                a[u][2] = f2tf32(As[b][mb][ks * 8 + tig + 4]);
                a[u][3] = f2tf32(As[b][mb + 8][ks * 8 + tig + 4]);
            }
            #pragma unroll
            for (int nt = 0; nt < NTW; ++nt) {
                uint32_t b0 = f2tf32(Bs[b][ks * 8 + tig][wn * (BN / 2) + nt * 8 + gid]);
                uint32_t b1 = f2tf32(Bs[b][ks * 8 + tig + 4][wn * (BN / 2) + nt * 8 + gid]);
                mma16n8k8(acc[0][nt], a[0], b0, b1);
                mma16n8k8(acc[1][nt], a[1], b0, b1);
            }
        }
        __syncthreads();
    }

    #pragma unroll
    for (int u = 0; u < 2; ++u) {
        const int m0 = bm + wm * 32 + u * 16 + gid;
        const float bv0 = bias[m0];
        const float bv1 = bias[m0 + 8];
        #pragma unroll
        for (int nt = 0; nt < NTW; ++nt) {
            const int n = bn + wn * (BN / 2) + nt * 8 + tig * 2;
            float2 r0 = make_float2(acc[u][nt][0] + bv0, acc[u][nt][1] + bv0);
            float2 r1 = make_float2(acc[u][nt][2] + bv1, acc[u][nt][3] + bv1);
            *(float2*)(C + (size_t)m0 * N + n)       = r0;
            *(float2*)(C + (size_t)(m0 + 8) * N + n) = r1;
        }
    }
}

// ---------------------------------------------------------------------------
// Kernel 3: fp16 mma.sync (m16n8k16) flash attention, fp32 accum.
// QB=256, 8 warps, grid (16, 8) = 128 CTAs. KB=64 keys/tile, 64 tiles.
// smem (32-bit words): Ksm[2][64][20] (half2 dim-pairs per key),
//                      Vsm[2][32][36] (half2 key-pairs per dim),
//                      Psm[8][32][36] (per-warp P half2 / fp32 O epilogue).
// exp via MUFU ex2.approx; l via ones-column MMA (no FADD stream, no shfl).
// One __syncthreads per tile (manual reg double-buffer staging).
// dyn smem: (2*64*20 + 2*32*36 + 8*32*36)*4 = 56320 B.
// ---------------------------------------------------------------------------
__global__ __launch_bounds__(256) void attn_mma(
    const float* __restrict__ qkv, float* __restrict__ out)
{
    extern __shared__ uint32_t dsm[];
    uint32_t (*Ksm)[64][20] = (uint32_t(*)[64][20])dsm;
    uint32_t (*Vsm)[32][36] = (uint32_t(*)[32][36])(dsm + 2 * 64 * 20);
    uint32_t* Psm = dsm + 2 * 64 * 20 + 2 * 32 * 36;

    const int tid  = threadIdx.x;
    const int w    = tid >> 5;
    const int lane = tid & 31;
    const int gid  = lane >> 2;
    const int tig  = lane & 3;
    const int h    = blockIdx.y;
    const int n0   = blockIdx.x * QB;

    const float SC = 0.17677669529663688f * 1.4426950408889634f; // hd^-0.5 * log2e

    const float* qb = qkv + (size_t)(h * HD) * NSP;
    const float* kb = qkv + (size_t)(CCH + h * HD) * NSP;
    const float* vb = qkv + (size_t)(2 * CCH + h * HD) * NSP;

    // staging thread mapping
    const int kkey = tid & 63;            // K: key index
    const int kdp  = (tid >> 6) << 2;     // K: dim-pair base (4 pairs)
    const int vdim = tid >> 3;            // V: dim index
    const int vkb  = (tid & 7) << 3;      // V: key base (8 keys)

    float  krf[8];
    float4 vrf[2];
    auto ldg_tile = [&](int j0) {
        #pragma unroll
        for (int p = 0; p < 4; ++p) {
            krf[2 * p]     = kb[(size_t)(2 * (kdp + p))     * NSP + j0 + kkey];
            krf[2 * p + 1] = kb[(size_t)(2 * (kdp + p) + 1) * NSP + j0 + kkey];
        }
        vrf[0] = *(const float4*)(vb + (size_t)vdim * NSP + j0 + vkb);
        vrf[1] = *(const float4*)(vb + (size_t)vdim * NSP + j0 + vkb + 4);
    };
    auto sts_tile = [&](int b) {
        #pragma unroll
        for (int p = 0; p < 4; ++p)
            Ksm[b][kkey][kdp + p] = packh2(krf[2 * p], krf[2 * p + 1]);
        const int kp = vkb >> 1;
        Vsm[b][vdim][kp]     = packh2(vrf[0].x, vrf[0].y);
        Vsm[b][vdim][kp + 1] = packh2(vrf[0].z, vrf[0].w);
        Vsm[b][vdim][kp + 2] = packh2(vrf[1].x, vrf[1].y);
        Vsm[b][vdim][kp + 3] = packh2(vrf[1].z, vrf[1].w);
    };

    ldg_tile(0);

    // Q fragments (fp16, pre-scaled into log2 domain): [u][ks][4]
    uint32_t qa[2][2][4];
    #pragma unroll
    for (int u = 0; u < 2; ++u) {
        const int rl = n0 + w * 32 + u * 16 + gid;
        #pragma unroll
        for (int ks = 0; ks < 2; ++ks) {
            const int d0 = ks * 16 + 2 * tig;
            qa[u][ks][0] = packh2(qb[(size_t)d0 * NSP + rl] * SC,
                                  qb[(size_t)(d0 + 1) * NSP + rl] * SC);
            qa[u][ks][1] = packh2(qb[(size_t)d0 * NSP + rl + 8] * SC,
                                  qb[(size_t)(d0 + 1) * NSP + rl + 8] * SC);
            qa[u][ks][2] = packh2(qb[(size_t)(d0 + 8) * NSP + rl] * SC,
                                  qb[(size_t)(d0 + 9) * NSP + rl] * SC);
            qa[u][ks][3] = packh2(qb[(size_t)(d0 + 8) * NSP + rl + 8] * SC,
                                  qb[(size_t)(d0 + 9) * NSP + rl + 8] * SC);
        }
    }

    float o[2][4][4] = {};
    float lacc[2][4] = {};
    const uint32_t ONES = 0x3C003C00u;   // half2(1,1)
    uint32_t* Pw = Psm + w * 32 * 36;

    const int NT = NSP / KB;   // 64 tiles
    for (int t = 0; t < NT; ++t) {
        const int b = t & 1;
        sts_tile(b);
        if (t + 1 < NT) ldg_tile((t + 1) * KB);
        __syncthreads();

        // S = Q@K^T (fp16 MMA) fused with MUFU exp2 softmax, P -> smem half2
        #pragma unroll
        for (int nt = 0; nt < 8; ++nt) {
            float s0[4] = {}, s1[4] = {};
            #pragma unroll
            for (int ks = 0; ks < 2; ++ks) {
                uint32_t b0 = Ksm[b][nt * 8 + gid][ks * 8 + tig];
                uint32_t b1 = Ksm[b][nt * 8 + gid][ks * 8 + tig + 4];
                mmaf16(s0, qa[0][ks], b0, b1);
                mmaf16(s1, qa[1][ks], b0, b1);
            }
            const int wp = nt * 4 + tig;
            Pw[gid * 36 + wp]        = packh2(ex2(s0[0]), ex2(s0[1]));
            Pw[(gid + 8) * 36 + wp]  = packh2(ex2(s0[2]), ex2(s0[3]));
            Pw[(gid + 16) * 36 + wp] = packh2(ex2(s1[0]), ex2(s1[1]));
            Pw[(gid + 24) * 36 + wp] = packh2(ex2(s1[2]), ex2(s1[3]));
        }
        __syncwarp();

        // l += P@1 (ones-MMA) and O += P@V
        #pragma unroll
        for (int ks = 0; ks < 4; ++ks) {
            uint32_t a0[4], a1[4];
            const int wc = ks * 8 + tig;
            a0[0] = Pw[gid * 36 + wc];
            a0[1] = Pw[(gid + 8) * 36 + wc];
            a0[2] = Pw[gid * 36 + wc + 4];
            a0[3] = Pw[(gid + 8) * 36 + wc + 4];
            a1[0] = Pw[(gid + 16) * 36 + wc];
            a1[1] = Pw[(gid + 24) * 36 + wc];
            a1[2] = Pw[(gid + 16) * 36 + wc + 4];
            a1[3] = Pw[(gid + 24) * 36 + wc + 4];
            mmaf16(lacc[0], a0, ONES, ONES);
            mmaf16(lacc[1], a1, ONES, ONES);
            #pragma unroll
            for (int nt = 0; nt < 4; ++nt) {
                uint32_t b0 = Vsm[b][nt * 8 + gid][wc];
                uint32_t b1 = Vsm[b][nt * 8 + gid][wc + 4];
                mmaf16(o[0][nt], a0, b0, b1);
                mmaf16(o[1][nt], a1, b0, b1);
            }
        }
    }

    // normalize (rowsum in lacc: c0 = row gid, c2 = row gid+8)
    const float il[2][2] = { {1.f / lacc[0][0], 1.f / lacc[0][2]},
                             {1.f / lacc[1][0], 1.f / lacc[1][2]} };

    __syncthreads();   // all tiles done; Psm reuse as fp32 O staging
    float* Pf = (float*)Pw;
    #pragma unroll
    for (int u = 0; u < 2; ++u)
        #pragma unroll
        for (int nt = 0; nt < 4; ++nt) {
            const int c0 = nt * 8 + 2 * tig;
            *(float2*)&Pf[(u * 16 + gid) * 36 + c0] =
                make_float2(o[u][nt][0] * il[u][0], o[u][nt][1] * il[u][0]);
            *(float2*)&Pf[(u * 16 + gid + 8) * 36 + c0] =
                make_float2(o[u][nt][2] * il[u][1], o[u][nt][3] * il[u][1]);
        }
    __syncwarp();

    const float* Pr = (const float*)Pw + lane * 36;
    float* ob = out + (size_t)(h * HD) * NSP + n0 + w * 32 + lane;
    #pragma unroll
    for (int d = 0; d < 32; ++d)
        ob[(size_t)d * NSP] = Pr[d];
}

// ---------------------------------------------------------------------------
extern "C" void kernel_launch(void* const* d_in, const int* in_sizes, int n_in,
                              void* d_out, int out_size)
{
    const float* x      = (const float*)d_in[0];
    const float* w_dw   = (const float*)d_in[1];
    const float* b_dw   = (const float*)d_in[2];
    const float* w_qkv  = (const float*)d_in[3];
    const float* b_qkv  = (const float*)d_in[4];
    const float* w_proj = (const float*)d_in[5];
    const float* b_proj = (const float*)d_in[6];
    float* outp = (float*)d_out;

    float *py, *pqkv, *patt;
    cudaGetSymbolAddress((void**)&py,   g_y);
    cudaGetSymbolAddress((void**)&pqkv, g_qkv);
    cudaGetSymbolAddress((void**)&patt, g_att);

    const int GEMM128_SMEM = (2 * 128 * 36 + 2 * 32 * 136) * 4;  // 71680 B
    const int GEMM64_SMEM  = (2 * 128 * 36 + 2 * 32 * 72)  * 4;  // 55296 B
    const int ATTN_SMEM    = (2 * 64 * 20 + 2 * 32 * 36 + 8 * 32 * 36) * 4; // 56320 B
    static int smem_set = 0;
    if (!smem_set) {
        cudaFuncSetAttribute(gemm_tc<128>, cudaFuncAttributeMaxDynamicSharedMemorySize, GEMM128_SMEM);
        cudaFuncSetAttribute(gemm_tc<64>,  cudaFuncAttributeMaxDynamicSharedMemorySize, GEMM64_SMEM);
        cudaFuncSetAttribute(attn_mma,     cudaFuncAttributeMaxDynamicSharedMemorySize, ATTN_SMEM);
        smem_set = 1;
    }

    conv_in_kernel<<<CCH, 256>>>(x, w_dw, b_dw, py);
    gemm_tc<128><<<dim3(NSP / 128, (3 * CCH) / 128), 256, GEMM128_SMEM>>>(w_qkv, py, b_qkv, pqkv, 3 * CCH, NSP, CCH);
    attn_mma<<<dim3(NSP / QB, NHEADS), 256, ATTN_SMEM>>>(pqkv, patt);
    gemm_tc<64><<<dim3(NSP / 64, CCH / 128), 256, GEMM64_SMEM>>>(w_proj, patt, b_proj, outp, CCH, NSP, CCH);
}

// round 8
// speedup vs baseline: 2.2232x; 1.1484x over previous
#include <cuda_runtime.h>
#include <cuda_fp16.h>
#include <cstdint>

#define NSP 4096      // H*W*D = 16^3
#define CCH 256
#define NHEADS 8
#define HD 32
#define QB 256
#define KB 128

// scratch, all channel-pair-interleaved half2 words: X2[c/2][n] = half2(X[c],X[c+1])
__device__ uint32_t g_y2[(CCH / 2) * NSP];
__device__ uint32_t g_qkv2[(3 * CCH / 2) * NSP];   // Q rows pre-scaled by hd^-.5*log2e
__device__ uint32_t g_att2[(CCH / 2) * NSP];

// ---------------------------------------------------------------------------
__device__ __forceinline__ uint32_t smem_u32(const void* p) {
    uint32_t a;
    asm("{ .reg .u64 t; cvta.to.shared.u64 t, %1; cvt.u32.u64 %0, t; }" : "=r"(a) : "l"(p));
    return a;
}
__device__ __forceinline__ void cp16(uint32_t saddr, const void* g) {
    asm volatile("cp.async.cg.shared.global [%0], [%1], 16;" :: "r"(saddr), "l"(g));
}
#define CP_COMMIT() asm volatile("cp.async.commit_group;" ::: "memory")
#define CP_WAIT0()  asm volatile("cp.async.wait_group 0;" ::: "memory")
#define CP_WAIT1()  asm volatile("cp.async.wait_group 1;" ::: "memory")

__device__ __forceinline__ void mmaf16(float c[4], const uint32_t a[4],
                                       uint32_t b0, uint32_t b1) {
    asm("mma.sync.aligned.m16n8k16.row.col.f32.f16.f16.f32 "
        "{%0,%1,%2,%3}, {%4,%5,%6,%7}, {%8,%9}, {%0,%1,%2,%3};"
        : "+f"(c[0]), "+f"(c[1]), "+f"(c[2]), "+f"(c[3])
        : "r"(a[0]), "r"(a[1]), "r"(a[2]), "r"(a[3]), "r"(b0), "r"(b1));
}
__device__ __forceinline__ uint32_t packh2(float lo, float hi) {
    __half2 h = __float22half2_rn(make_float2(lo, hi));
    return *reinterpret_cast<uint32_t*>(&h);
}
__device__ __forceinline__ float ex2(float s) {
    float r; asm("ex2.approx.f32 %0, %1;" : "=f"(r) : "f"(s)); return r;
}
__device__ __forceinline__ uint32_t prmt(uint32_t a, uint32_t b, uint32_t sel) {
    uint32_t d; asm("prmt.b32 %0, %1, %2, %3;" : "=r"(d) : "r"(a), "r"(b), "r"(sel)); return d;
}

// ---------------------------------------------------------------------------
// Kernel 1: depthwise 3x3x3 conv + bias + InstanceNorm; 2 channels/block,
// two sequential passes; output packed half2 pair-interleaved.
// ---------------------------------------------------------------------------
__global__ __launch_bounds__(256) void conv_in_kernel(
    const float* __restrict__ x, const float* __restrict__ wdw,
    const float* __restrict__ bdw, uint32_t* __restrict__ y2)
{
    const int cp  = blockIdx.x;      // channel pair
    const int tid = threadIdx.x;
    __shared__ float xs[NSP];
    __shared__ float red[512];

    const int w  = tid >> 4;
    const int dd = tid & 15;

    float prev[16];
    float out[16];

    for (int s = 0; s < 2; ++s) {
        const int c = 2 * cp + s;
        __syncthreads();
        const float4* xg = (const float4*)(x + (size_t)c * NSP);
        float4* xs4 = (float4*)xs;
        #pragma unroll
        for (int i = 0; i < 4; ++i) xs4[tid + 256 * i] = xg[tid + 256 * i];

        float wr[27];
        #pragma unroll
        for (int i = 0; i < 27; ++i) wr[i] = wdw[c * 27 + i];
        const float bias = bdw[c];
        __syncthreads();

        float sm = 0.f, s2 = 0.f;
        for (int hh = 0; hh < 16; ++hh) {
            float acc = bias;
            #pragma unroll
            for (int i = 0; i < 3; ++i) {
                int ih = hh + i - 1;
                if ((unsigned)ih < 16u) {
                    #pragma unroll
                    for (int j = 0; j < 3; ++j) {
                        int iw = w + j - 1;
                        if ((unsigned)iw < 16u) {
                            #pragma unroll
                            for (int k = 0; k < 3; ++k) {
                                int id = dd + k - 1;
                                if ((unsigned)id < 16u)
                                    acc = fmaf(xs[ih * 256 + iw * 16 + id], wr[i * 9 + j * 3 + k], acc);
                            }
                        }
                    }
                }
            }
            out[hh] = acc;
            sm += acc;
            s2 = fmaf(acc, acc, s2);
        }

        red[tid] = sm; red[256 + tid] = s2;
        __syncthreads();
        for (int st = 128; st > 0; st >>= 1) {
            if (tid < st) { red[tid] += red[tid + st]; red[256 + tid] += red[256 + tid + st]; }
            __syncthreads();
        }
        const float mean = red[0] * (1.0f / NSP);
        const float var  = red[256] * (1.0f / NSP) - mean * mean;
        const float rs   = rsqrtf(var + 1e-5f);

        if (s == 0) {
            for (int hh = 0; hh < 16; ++hh) prev[hh] = (out[hh] - mean) * rs;
        } else {
            for (int hh = 0; hh < 16; ++hh)
                y2[(size_t)cp * NSP + hh * 256 + tid] = packh2(prev[hh], (out[hh] - mean) * rs);
        }
    }
}

// ---------------------------------------------------------------------------
// Kernel 2/4: fp16 mma.sync GEMM. C[M,N] = A[M,K] * B[K,N] + bias[m].
// A fp32 weights (cvt+k-pair-pack on stage); B half2 pair-interleaved (cp.async).
// BM=128, BK=32, 8 warps (4m x 2n). HOUT: write half2 pair-interleaved C with
// optional per-row scale (qsc for rows<256); else fp32.
// smem: As[2][128][20] + Bs[2][16][BN+8] words; epilogue reuses as half C tile.
// ---------------------------------------------------------------------------
template<int BN, bool HOUT>
__global__ __launch_bounds__(256) void gemm_h(
    const float* __restrict__ A, const uint32_t* __restrict__ B2,
    const float* __restrict__ bias, void* __restrict__ Cout,
    int M, int N, int K, float qsc)
{
    constexpr int BSW = BN + 8;          // Bs row stride (words) & C-stage stride (halves)
    constexpr int NTW = BN / 16;
    extern __shared__ uint32_t gsm[];
    auto As = (uint32_t(*)[128][20])gsm;
    auto Bs = (uint32_t(*)[16][BSW])(gsm + 2 * 128 * 20);

    const int tid  = threadIdx.x;
    const int w    = tid >> 5;
    const int lane = tid & 31;
    const int gid  = lane >> 2;
    const int tig  = lane & 3;
    const int wm   = w >> 1;
    const int wn   = w & 1;
    const int bm   = blockIdx.y * 128;
    const int bn   = blockIdx.x * BN;

    const int am  = tid >> 1;
    const int akh = tid & 1;
    const int bkp = tid >> 4;
    const int bc  = tid & 15;

    float acc[2][NTW][4] = {};

    auto stage = [&](int b, int k0) {
        const float* ar = A + (size_t)(bm + am) * K + k0 + akh * 16;
        #pragma unroll
        for (int p = 0; p < 4; ++p) {
            float4 f = *(const float4*)(ar + p * 4);
            As[b][am][akh * 8 + 2 * p]     = packh2(f.x, f.y);
            As[b][am][akh * 8 + 2 * p + 1] = packh2(f.z, f.w);
        }
        const uint32_t* br = B2 + (size_t)((k0 >> 1) + bkp) * N + bn;
        if (BN == 64) {
            cp16(smem_u32(&Bs[b][bkp][bc * 4]), br + bc * 4);
        } else {
            cp16(smem_u32(&Bs[b][bkp][bc * 8]),     br + bc * 8);
            cp16(smem_u32(&Bs[b][bkp][bc * 8 + 4]), br + bc * 8 + 4);
        }
        CP_COMMIT();
    };

    const int NT = K / 32;
    stage(0, 0);

    for (int t = 0; t < NT; ++t) {
        if (t + 1 < NT) { stage((t + 1) & 1, (t + 1) * 32); CP_WAIT1(); }
        else            { CP_WAIT0(); }
        __syncthreads();

        const int b = t & 1;
        #pragma unroll
        for (int ks = 0; ks < 2; ++ks) {
            uint32_t a[2][4];
            #pragma unroll
            for (int u = 0; u < 2; ++u) {
                const int mb = wm * 32 + u * 16 + gid;
                a[u][0] = As[b][mb][ks * 8 + tig];
                a[u][1] = As[b][mb + 8][ks * 8 + tig];
                a[u][2] = As[b][mb][ks * 8 + tig + 4];
                a[u][3] = As[b][mb + 8][ks * 8 + tig + 4];
            }
            #pragma unroll
            for (int nt = 0; nt < NTW; ++nt) {
                uint32_t b0 = Bs[b][ks * 8 + tig][wn * (BN / 2) + nt * 8 + gid];
                uint32_t b1 = Bs[b][ks * 8 + tig + 4][wn * (BN / 2) + nt * 8 + gid];
                mmaf16(acc[0][nt], a[0], b0, b1);
                mmaf16(acc[1][nt], a[1], b0, b1);
            }
        }
        __syncthreads();
    }

    if (HOUT) {
        // stage half C tile in smem (reuses As/Bs), then pack (m,m+1) pairs
        const float sc = (bm < 256) ? qsc : 1.0f;
        uint32_t* Cs32 = gsm;                    // [128][BSW/2] words
        constexpr int CSW = BSW / 2;
        #pragma unroll
        for (int u = 0; u < 2; ++u) {
            const int r0 = wm * 32 + u * 16 + gid;
            const float bv0 = bias[bm + r0];
            const float bv1 = bias[bm + r0 + 8];
            #pragma unroll
            for (int nt = 0; nt < NTW; ++nt) {
                const int wc = wn * (BN / 4) + nt * 4 + tig;
                Cs32[r0 * CSW + wc]       = packh2((acc[u][nt][0] + bv0) * sc,
                                                   (acc[u][nt][1] + bv0) * sc);
                Cs32[(r0 + 8) * CSW + wc] = packh2((acc[u][nt][2] + bv1) * sc,
                                                   (acc[u][nt][3] + bv1) * sc);
            }
        }
        __syncthreads();
        const unsigned short* Ch = (const unsigned short*)gsm;
        uint32_t* C2 = (uint32_t*)Cout;
        const int n  = tid & (BN - 1);
        const int rg = tid / BN;
        constexpr int RPT = BN / 4;              // row-pairs per thread group
        #pragma unroll
        for (int p = 0; p < RPT; ++p) {
            const int r = rg * RPT + p;
            uint32_t lo = Ch[(2 * r) * BSW + n];
            uint32_t hi = Ch[(2 * r + 1) * BSW + n];
            C2[(size_t)((bm >> 1) + r) * N + bn + n] = lo | (hi << 16);
        }
    } else {
        float* C = (float*)Cout;
        #pragma unroll
        for (int u = 0; u < 2; ++u) {
            const int m0 = bm + wm * 32 + u * 16 + gid;
            const float bv0 = bias[m0];
            const float bv1 = bias[m0 + 8];
            #pragma unroll
            for (int nt = 0; nt < NTW; ++nt) {
                const int n = bn + wn * (BN / 2) + nt * 8 + tig * 2;
                *(float2*)(C + (size_t)m0 * N + n) =
                    make_float2(acc[u][nt][0] + bv0, acc[u][nt][1] + bv0);
                *(float2*)(C + (size_t)(m0 + 8) * N + n) =
                    make_float2(acc[u][nt][2] + bv1, acc[u][nt][3] + bv1);
            }
        }
    }
}

// ---------------------------------------------------------------------------
// Kernel 3: fp16 flash attention, KB=128 keys/tile (32 tiles), QB=256, 8 warps.
// K tile: pure cp.async (gmem dim-pair rows == smem layout [dimpair][key]).
// V tile: LDG.128 + PRMT 2x2 transpose (dim-pairs -> key-pairs).
// Q frags: plain LDG.32 (pre-scaled in qkv epilogue).
// smem: Ksm[2][16][136] + Vsm[2][32][68] + Psm[8][32][68] = 104448 B.
// ---------------------------------------------------------------------------
__global__ __launch_bounds__(256) void attn_h(
    const uint32_t* __restrict__ qkv2, uint32_t* __restrict__ out2)
{
    extern __shared__ uint32_t dsm[];
    auto Ksm = (uint32_t(*)[16][136])dsm;
    auto Vsm = (uint32_t(*)[32][68])(dsm + 2 * 16 * 136);
    uint32_t* Psm = dsm + 2 * 16 * 136 + 2 * 32 * 68;

    const int tid  = threadIdx.x;
    const int w    = tid >> 5;
    const int lane = tid & 31;
    const int gid  = lane >> 2;
    const int tig  = lane & 3;
    const int h    = blockIdx.y;
    const int n0   = blockIdx.x * QB;

    const uint32_t* Qb = qkv2 + (size_t)(h * 16) * NSP;
    const uint32_t* Kb = qkv2 + (size_t)(128 + h * 16) * NSP;
    const uint32_t* Vb = qkv2 + (size_t)(256 + h * 16) * NSP;

    const int sp = tid >> 4;          // 0..15: K row / V dim-pair
    const int sc = (tid & 15) * 8;    // K col base / V key base

    uint4 vr0, vr1;
    auto ldg_V = [&](int j0) {
        vr0 = *(const uint4*)(Vb + (size_t)sp * NSP + j0 + sc);
        vr1 = *(const uint4*)(Vb + (size_t)sp * NSP + j0 + sc + 4);
    };
    auto sts_V = [&](int b) {
        const int kp = sc >> 1;
        Vsm[b][2 * sp][kp]         = prmt(vr0.x, vr0.y, 0x5410);
        Vsm[b][2 * sp + 1][kp]     = prmt(vr0.x, vr0.y, 0x7632);
        Vsm[b][2 * sp][kp + 1]     = prmt(vr0.z, vr0.w, 0x5410);
        Vsm[b][2 * sp + 1][kp + 1] = prmt(vr0.z, vr0.w, 0x7632);
        Vsm[b][2 * sp][kp + 2]     = prmt(vr1.x, vr1.y, 0x5410);
        Vsm[b][2 * sp + 1][kp + 2] = prmt(vr1.x, vr1.y, 0x7632);
        Vsm[b][2 * sp][kp + 3]     = prmt(vr1.z, vr1.w, 0x5410);
        Vsm[b][2 * sp + 1][kp + 3] = prmt(vr1.z, vr1.w, 0x7632);
    };
    auto cp_K = [&](int b, int j0) {
        const uint32_t* src = Kb + (size_t)sp * NSP + j0 + sc;
        cp16(smem_u32(&Ksm[b][sp][sc]), src);
        cp16(smem_u32(&Ksm[b][sp][sc + 4]), src + 4);
        CP_COMMIT();
    };

    cp_K(0, 0);
    ldg_V(0);

    // Q fragments (pre-scaled half2 dim-pairs)
    uint32_t qa[2][2][4];
    #pragma unroll
    for (int u = 0; u < 2; ++u) {
        const int rl = n0 + w * 32 + u * 16 + gid;
        #pragma unroll
        for (int ks = 0; ks < 2; ++ks) {
            const uint32_t* q0 = Qb + (size_t)(ks * 8 + tig) * NSP + rl;
            const uint32_t* q1 = Qb + (size_t)(ks * 8 + tig + 4) * NSP + rl;
            qa[u][ks][0] = q0[0];
            qa[u][ks][1] = q0[8];
            qa[u][ks][2] = q1[0];
            qa[u][ks][3] = q1[8];
        }
    }

    float o[2][4][4] = {};
    float lacc[2][4] = {};
    const uint32_t ONES = 0x3C003C00u;
    uint32_t* Pw = Psm + w * 32 * 68;

    const int NT = NSP / KB;   // 32 tiles
    for (int t = 0; t < NT; ++t) {
        const int b = t & 1;
        sts_V(b);
        CP_WAIT0();
        __syncthreads();
        if (t + 1 < NT) { cp_K(b ^ 1, (t + 1) * KB); ldg_V((t + 1) * KB); }

        // S = Q@K^T + MUFU exp2 -> P (half2 key-pairs, per-warp smem)
        #pragma unroll
        for (int nt = 0; nt < 16; ++nt) {
            float s0[4] = {}, s1[4] = {};
            #pragma unroll
            for (int ks = 0; ks < 2; ++ks) {
                uint32_t b0 = Ksm[b][ks * 8 + tig][nt * 8 + gid];
                uint32_t b1 = Ksm[b][ks * 8 + tig + 4][nt * 8 + gid];
                mmaf16(s0, qa[0][ks], b0, b1);
                mmaf16(s1, qa[1][ks], b0, b1);
            }
            const int wp = nt * 4 + tig;
            Pw[gid * 68 + wp]        = packh2(ex2(s0[0]), ex2(s0[1]));
            Pw[(gid + 8) * 68 + wp]  = packh2(ex2(s0[2]), ex2(s0[3]));
            Pw[(gid + 16) * 68 + wp] = packh2(ex2(s1[0]), ex2(s1[1]));
            Pw[(gid + 24) * 68 + wp] = packh2(ex2(s1[2]), ex2(s1[3]));
        }
        __syncwarp();

        // l += P@1 ; O += P@V
        #pragma unroll
        for (int ks = 0; ks < 8; ++ks) {
            uint32_t a0[4], a1[4];
            const int wc = ks * 8 + tig;
            a0[0] = Pw[gid * 68 + wc];
            a0[1] = Pw[(gid + 8) * 68 + wc];
            a0[2] = Pw[gid * 68 + wc + 4];
            a0[3] = Pw[(gid + 8) * 68 + wc + 4];
            a1[0] = Pw[(gid + 16) * 68 + wc];
            a1[1] = Pw[(gid + 24) * 68 + wc];
            a1[2] = Pw[(gid + 16) * 68 + wc + 4];
            a1[3] = Pw[(gid + 24) * 68 + wc + 4];
            mmaf16(lacc[0], a0, ONES, ONES);
            mmaf16(lacc[1], a1, ONES, ONES);
            #pragma unroll
            for (int nt = 0; nt < 4; ++nt) {
                uint32_t b0 = Vsm[b][nt * 8 + gid][wc];
                uint32_t b1 = Vsm[b][nt * 8 + gid][wc + 4];
                mmaf16(o[0][nt], a0, b0, b1);
                mmaf16(o[1][nt], a1, b0, b1);
            }
        }
    }

    const float il[2][2] = { {1.f / lacc[0][0], 1.f / lacc[0][2]},
                             {1.f / lacc[1][0], 1.f / lacc[1][2]} };

    __syncthreads();
    float* Pf = (float*)Pw;
    #pragma unroll
    for (int u = 0; u < 2; ++u)
        #pragma unroll
        for (int nt = 0; nt < 4; ++nt) {
            const int c0 = nt * 8 + 2 * tig;
            *(float2*)&Pf[(u * 16 + gid) * 36 + c0] =
                make_float2(o[u][nt][0] * il[u][0], o[u][nt][1] * il[u][0]);
            *(float2*)&Pf[(u * 16 + gid + 8) * 36 + c0] =
                make_float2(o[u][nt][2] * il[u][1], o[u][nt][3] * il[u][1]);
        }
    __syncwarp();

    const float* Pr = (const float*)Pw + lane * 36;
    uint32_t* ob = out2 + (size_t)(h * 16) * NSP + n0 + w * 32 + lane;
    #pragma unroll
    for (int dp = 0; dp < 16; ++dp) {
        float2 v = *(const float2*)&Pr[2 * dp];
        ob[(size_t)dp * NSP] = packh2(v.x, v.y);
    }
}

// ---------------------------------------------------------------------------
extern "C" void kernel_launch(void* const* d_in, const int* in_sizes, int n_in,
                              void* d_out, int out_size)
{
    const float* x      = (const float*)d_in[0];
    const float* w_dw   = (const float*)d_in[1];
    const float* b_dw   = (const float*)d_in[2];
    const float* w_qkv  = (const float*)d_in[3];
    const float* b_qkv  = (const float*)d_in[4];
    const float* w_proj = (const float*)d_in[5];
    const float* b_proj = (const float*)d_in[6];
    float* outp = (float*)d_out;

    uint32_t *py2, *pqkv2, *patt2;
    cudaGetSymbolAddress((void**)&py2,   g_y2);
    cudaGetSymbolAddress((void**)&pqkv2, g_qkv2);
    cudaGetSymbolAddress((void**)&patt2, g_att2);

    const float SC = 0.17677669529663688f * 1.4426950408889634f; // hd^-0.5 * log2e
    const int GEMM128_SMEM = (2 * 128 * 20 + 2 * 16 * 136) * 4;  // 37888 B
    const int GEMM64_SMEM  = (2 * 128 * 20 + 2 * 16 * 72)  * 4;  // 29696 B
    const int ATTN_SMEM    = (2 * 16 * 136 + 2 * 32 * 68 + 8 * 32 * 68) * 4; // 104448 B
    static int smem_set = 0;
    if (!smem_set) {
        cudaFuncSetAttribute(gemm_h<128, true>, cudaFuncAttributeMaxDynamicSharedMemorySize, GEMM128_SMEM);
        cudaFuncSetAttribute(gemm_h<64, false>, cudaFuncAttributeMaxDynamicSharedMemorySize, GEMM64_SMEM);
        cudaFuncSetAttribute(attn_h,            cudaFuncAttributeMaxDynamicSharedMemorySize, ATTN_SMEM);
        smem_set = 1;
    }

    conv_in_kernel<<<CCH / 2, 256>>>(x, w_dw, b_dw, py2);
    gemm_h<128, true><<<dim3(NSP / 128, (3 * CCH) / 128), 256, GEMM128_SMEM>>>(
        w_qkv, py2, b_qkv, pqkv2, 3 * CCH, NSP, CCH, SC);
    attn_h<<<dim3(NSP / QB, NHEADS), 256, ATTN_SMEM>>>(pqkv2, patt2);
    gemm_h<64, false><<<dim3(NSP / 64, CCH / 128), 256, GEMM64_SMEM>>>(
        w_proj, patt2, b_proj, outp, CCH, NSP, CCH, 1.0f);
}

// round 9
// speedup vs baseline: 2.3428x; 1.0538x over previous
#include <cuda_runtime.h>
#include <cuda_fp16.h>
#include <cstdint>

#define NSP 4096      // H*W*D = 16^3
#define CCH 256
#define NHEADS 8
#define HD 32
#define QB 256
#define KB 128

// scratch, all channel-pair-interleaved half2 words: X2[c/2][n] = half2(X[c],X[c+1])
__device__ uint32_t g_y2[(CCH / 2) * NSP];
__device__ uint32_t g_qkv2[(3 * CCH / 2) * NSP];   // Q rows pre-scaled by hd^-.5*log2e
__device__ uint32_t g_att2[(CCH / 2) * NSP];

// ---------------------------------------------------------------------------
__device__ __forceinline__ uint32_t smem_u32(const void* p) {
    uint32_t a;
    asm("{ .reg .u64 t; cvta.to.shared.u64 t, %1; cvt.u32.u64 %0, t; }" : "=r"(a) : "l"(p));
    return a;
}
__device__ __forceinline__ void cp16(uint32_t saddr, const void* g) {
    asm volatile("cp.async.cg.shared.global [%0], [%1], 16;" :: "r"(saddr), "l"(g));
}
#define CP_COMMIT() asm volatile("cp.async.commit_group;" ::: "memory")
#define CP_WAIT0()  asm volatile("cp.async.wait_group 0;" ::: "memory")
#define CP_WAIT1()  asm volatile("cp.async.wait_group 1;" ::: "memory")

__device__ __forceinline__ void mmaf16(float c[4], const uint32_t a[4],
                                       uint32_t b0, uint32_t b1) {
    asm("mma.sync.aligned.m16n8k16.row.col.f32.f16.f16.f32 "
        "{%0,%1,%2,%3}, {%4,%5,%6,%7}, {%8,%9}, {%0,%1,%2,%3};"
        : "+f"(c[0]), "+f"(c[1]), "+f"(c[2]), "+f"(c[3])
        : "r"(a[0]), "r"(a[1]), "r"(a[2]), "r"(a[3]), "r"(b0), "r"(b1));
}
__device__ __forceinline__ uint32_t packh2(float lo, float hi) {
    __half2 h = __float22half2_rn(make_float2(lo, hi));
    return *reinterpret_cast<uint32_t*>(&h);
}
__device__ __forceinline__ float ex2(float s) {
    float r; asm("ex2.approx.f32 %0, %1;" : "=f"(r) : "f"(s)); return r;
}
__device__ __forceinline__ uint32_t prmt(uint32_t a, uint32_t b, uint32_t sel) {
    uint32_t d; asm("prmt.b32 %0, %1, %2, %3;" : "=r"(d) : "r"(a), "r"(b), "r"(sel)); return d;
}

// ---------------------------------------------------------------------------
// Kernel 1: depthwise 3x3x3 conv + bias + InstanceNorm; 2 channels/block,
// two sequential passes; output packed half2 pair-interleaved.
// ---------------------------------------------------------------------------
__global__ __launch_bounds__(256) void conv_in_kernel(
    const float* __restrict__ x, const float* __restrict__ wdw,
    const float* __restrict__ bdw, uint32_t* __restrict__ y2)
{
    const int cp  = blockIdx.x;      // channel pair
    const int tid = threadIdx.x;
    __shared__ float xs[NSP];
    __shared__ float red[512];

    const int w  = tid >> 4;
    const int dd = tid & 15;

    float prev[16];
    float out[16];

    for (int s = 0; s < 2; ++s) {
        const int c = 2 * cp + s;
        __syncthreads();
        const float4* xg = (const float4*)(x + (size_t)c * NSP);
        float4* xs4 = (float4*)xs;
        #pragma unroll
        for (int i = 0; i < 4; ++i) xs4[tid + 256 * i] = xg[tid + 256 * i];

        float wr[27];
        #pragma unroll
        for (int i = 0; i < 27; ++i) wr[i] = wdw[c * 27 + i];
        const float bias = bdw[c];
        __syncthreads();

        float sm = 0.f, s2 = 0.f;
        for (int hh = 0; hh < 16; ++hh) {
            float acc = bias;
            #pragma unroll
            for (int i = 0; i < 3; ++i) {
                int ih = hh + i - 1;
                if ((unsigned)ih < 16u) {
                    #pragma unroll
                    for (int j = 0; j < 3; ++j) {
                        int iw = w + j - 1;
                        if ((unsigned)iw < 16u) {
                            #pragma unroll
                            for (int k = 0; k < 3; ++k) {
                                int id = dd + k - 1;
                                if ((unsigned)id < 16u)
                                    acc = fmaf(xs[ih * 256 + iw * 16 + id], wr[i * 9 + j * 3 + k], acc);
                            }
                        }
                    }
                }
            }
            out[hh] = acc;
            sm += acc;
            s2 = fmaf(acc, acc, s2);
        }

        red[tid] = sm; red[256 + tid] = s2;
        __syncthreads();
        for (int st = 128; st > 0; st >>= 1) {
            if (tid < st) { red[tid] += red[tid + st]; red[256 + tid] += red[256 + tid + st]; }
            __syncthreads();
        }
        const float mean = red[0] * (1.0f / NSP);
        const float var  = red[256] * (1.0f / NSP) - mean * mean;
        const float rs   = rsqrtf(var + 1e-5f);

        if (s == 0) {
            for (int hh = 0; hh < 16; ++hh) prev[hh] = (out[hh] - mean) * rs;
        } else {
            for (int hh = 0; hh < 16; ++hh)
                y2[(size_t)cp * NSP + hh * 256 + tid] = packh2(prev[hh], (out[hh] - mean) * rs);
        }
    }
}

// ---------------------------------------------------------------------------
// Kernel 2/4: fp16 mma.sync GEMM, BK=64. C[M,N] = A[M,K]*B[K,N] + bias[m].
// A fp32 weights (cvt+k-pair-pack on stage); B half2 pair-interleaved (cp.async).
// BM=128, 8 warps (4m x 2n). HOUT: half2 pair-interleaved C with per-row scale
// (qsc for rows<256); else fp32.
// smem words: As[2][128][36] + Bs[2][32][BN+8].
// ---------------------------------------------------------------------------
template<int BN, bool HOUT>
__global__ __launch_bounds__(256) void gemm_h(
    const float* __restrict__ A, const uint32_t* __restrict__ B2,
    const float* __restrict__ bias, void* __restrict__ Cout,
    int M, int N, int K, float qsc)
{
    constexpr int BSW = BN + 8;
    constexpr int NTW = BN / 16;
    extern __shared__ uint32_t gsm[];
    auto As = (uint32_t(*)[128][36])gsm;
    auto Bs = (uint32_t(*)[32][BSW])(gsm + 2 * 128 * 36);

    const int tid  = threadIdx.x;
    const int w    = tid >> 5;
    const int lane = tid & 31;
    const int gid  = lane >> 2;
    const int tig  = lane & 3;
    const int wm   = w >> 1;
    const int wn   = w & 1;
    const int bm   = blockIdx.y * 128;
    const int bn   = blockIdx.x * BN;

    const int am  = tid >> 1;          // A row, 2 threads/row
    const int akh = tid & 1;           // A k-half (32 floats each)
    const int bkp = tid >> 3;          // B k-pair row 0..31
    const int bc  = (tid & 7) * (BN / 8);

    float acc[2][NTW][4] = {};

    auto stage = [&](int b, int k0) {
        const float* ar = A + (size_t)(bm + am) * K + k0 + akh * 32;
        #pragma unroll
        for (int p = 0; p < 8; ++p) {
            float4 f = *(const float4*)(ar + p * 4);
            As[b][am][akh * 16 + 2 * p]     = packh2(f.x, f.y);
            As[b][am][akh * 16 + 2 * p + 1] = packh2(f.z, f.w);
        }
        const uint32_t* br = B2 + (size_t)((k0 >> 1) + bkp) * N + bn + bc;
        #pragma unroll
        for (int p = 0; p < BN / 32; ++p)
            cp16(smem_u32(&Bs[b][bkp][bc + p * 4]), br + p * 4);
        CP_COMMIT();
    };

    const int NT = K / 64;
    stage(0, 0);

    for (int t = 0; t < NT; ++t) {
        if (t + 1 < NT) { stage((t + 1) & 1, (t + 1) * 64); CP_WAIT1(); }
        else            { CP_WAIT0(); }
        __syncthreads();

        const int b = t & 1;
        #pragma unroll
        for (int ks = 0; ks < 4; ++ks) {
            uint32_t a[2][4];
            #pragma unroll
            for (int u = 0; u < 2; ++u) {
                const int mb = wm * 32 + u * 16 + gid;
                a[u][0] = As[b][mb][ks * 8 + tig];
                a[u][1] = As[b][mb + 8][ks * 8 + tig];
                a[u][2] = As[b][mb][ks * 8 + tig + 4];
                a[u][3] = As[b][mb + 8][ks * 8 + tig + 4];
            }
            #pragma unroll
            for (int nt = 0; nt < NTW; ++nt) {
                uint32_t b0 = Bs[b][ks * 8 + tig][wn * (BN / 2) + nt * 8 + gid];
                uint32_t b1 = Bs[b][ks * 8 + tig + 4][wn * (BN / 2) + nt * 8 + gid];
                mmaf16(acc[0][nt], a[0], b0, b1);
                mmaf16(acc[1][nt], a[1], b0, b1);
            }
        }
        __syncthreads();
    }

    if (HOUT) {
        const float sc = (bm < 256) ? qsc : 1.0f;
        uint32_t* Cs32 = gsm;                    // [128][BSW/2] words
        constexpr int CSW = BSW / 2;
        #pragma unroll
        for (int u = 0; u < 2; ++u) {
            const int r0 = wm * 32 + u * 16 + gid;
            const float bv0 = bias[bm + r0];
            const float bv1 = bias[bm + r0 + 8];
            #pragma unroll
            for (int nt = 0; nt < NTW; ++nt) {
                const int wc = wn * (BN / 4) + nt * 4 + tig;
                Cs32[r0 * CSW + wc]       = packh2((acc[u][nt][0] + bv0) * sc,
                                                   (acc[u][nt][1] + bv0) * sc);
                Cs32[(r0 + 8) * CSW + wc] = packh2((acc[u][nt][2] + bv1) * sc,
                                                   (acc[u][nt][3] + bv1) * sc);
            }
        }
        __syncthreads();
        const unsigned short* Ch = (const unsigned short*)gsm;
        uint32_t* C2 = (uint32_t*)Cout;
        const int n  = tid & (BN - 1);
        const int rg = tid / BN;
        constexpr int RPT = BN / 4;
        #pragma unroll
        for (int p = 0; p < RPT; ++p) {
            const int r = rg * RPT + p;
            uint32_t lo = Ch[(2 * r) * BSW + n];
            uint32_t hi = Ch[(2 * r + 1) * BSW + n];
            C2[(size_t)((bm >> 1) + r) * N + bn + n] = lo | (hi << 16);
        }
    } else {
        float* C = (float*)Cout;
        #pragma unroll
        for (int u = 0; u < 2; ++u) {
            const int m0 = bm + wm * 32 + u * 16 + gid;
            const float bv0 = bias[m0];
            const float bv1 = bias[m0 + 8];
            #pragma unroll
            for (int nt = 0; nt < NTW; ++nt) {
                const int n = bn + wn * (BN / 2) + nt * 8 + tig * 2;
                *(float2*)(C + (size_t)m0 * N + n) =
                    make_float2(acc[u][nt][0] + bv0, acc[u][nt][1] + bv0);
                *(float2*)(C + (size_t)(m0 + 8) * N + n) =
                    make_float2(acc[u][nt][2] + bv1, acc[u][nt][3] + bv1);
            }
        }
    }
}

// ---------------------------------------------------------------------------
// Kernel 3: fp16 flash attention, fully fused per 16-key chunk.
// P lives in REGISTERS: QK C-fragment of two adjacent n-tiles IS the PV
// A-fragment (thread (gid,tig) holds S cols 2tig,2tig+1 of rows gid,gid+8).
// No P smem, no syncwarp. KB=128 keys/tile (32 tiles), QB=256, 8 warps.
// K tile: pure cp.async. V tile: LDG.128 + PRMT transpose to key-pairs.
// smem words: Ksm[2][16][136] + Vsm[2][32][68] + Psm[8][32][36] (epilogue only).
// ---------------------------------------------------------------------------
__global__ __launch_bounds__(256) void attn_h(
    const uint32_t* __restrict__ qkv2, uint32_t* __restrict__ out2)
{
    extern __shared__ uint32_t dsm[];
    auto Ksm = (uint32_t(*)[16][136])dsm;
    auto Vsm = (uint32_t(*)[32][68])(dsm + 2 * 16 * 136);
    uint32_t* Psm = dsm + 2 * 16 * 136 + 2 * 32 * 68;   // [8][32][36]

    const int tid  = threadIdx.x;
    const int w    = tid >> 5;
    const int lane = tid & 31;
    const int gid  = lane >> 2;
    const int tig  = lane & 3;
    const int h    = blockIdx.y;
    const int n0   = blockIdx.x * QB;

    const uint32_t* Qb = qkv2 + (size_t)(h * 16) * NSP;
    const uint32_t* Kb = qkv2 + (size_t)(128 + h * 16) * NSP;
    const uint32_t* Vb = qkv2 + (size_t)(256 + h * 16) * NSP;

    const int sp = tid >> 4;          // 0..15: K row / V dim-pair
    const int sc = (tid & 15) * 8;    // K col base / V key base

    uint4 vr0, vr1;
    auto ldg_V = [&](int j0) {
        vr0 = *(const uint4*)(Vb + (size_t)sp * NSP + j0 + sc);
        vr1 = *(const uint4*)(Vb + (size_t)sp * NSP + j0 + sc + 4);
    };
    auto sts_V = [&](int b) {
        const int kp = sc >> 1;
        Vsm[b][2 * sp][kp]         = prmt(vr0.x, vr0.y, 0x5410);
        Vsm[b][2 * sp + 1][kp]     = prmt(vr0.x, vr0.y, 0x7632);
        Vsm[b][2 * sp][kp + 1]     = prmt(vr0.z, vr0.w, 0x5410);
        Vsm[b][2 * sp + 1][kp + 1] = prmt(vr0.z, vr0.w, 0x7632);
        Vsm[b][2 * sp][kp + 2]     = prmt(vr1.x, vr1.y, 0x5410);
        Vsm[b][2 * sp + 1][kp + 2] = prmt(vr1.x, vr1.y, 0x7632);
        Vsm[b][2 * sp][kp + 3]     = prmt(vr1.z, vr1.w, 0x5410);
        Vsm[b][2 * sp + 1][kp + 3] = prmt(vr1.z, vr1.w, 0x7632);
    };
    auto cp_K = [&](int b, int j0) {
        const uint32_t* src = Kb + (size_t)sp * NSP + j0 + sc;
        cp16(smem_u32(&Ksm[b][sp][sc]), src);
        cp16(smem_u32(&Ksm[b][sp][sc + 4]), src + 4);
        CP_COMMIT();
    };

    cp_K(0, 0);
    ldg_V(0);

    // Q fragments (pre-scaled half2 dim-pairs)
    uint32_t qa[2][2][4];
    #pragma unroll
    for (int u = 0; u < 2; ++u) {
        const int rl = n0 + w * 32 + u * 16 + gid;
        #pragma unroll
        for (int ks = 0; ks < 2; ++ks) {
            const uint32_t* q0 = Qb + (size_t)(ks * 8 + tig) * NSP + rl;
            const uint32_t* q1 = Qb + (size_t)(ks * 8 + tig + 4) * NSP + rl;
            qa[u][ks][0] = q0[0];
            qa[u][ks][1] = q0[8];
            qa[u][ks][2] = q1[0];
            qa[u][ks][3] = q1[8];
        }
    }

    float o[2][4][4] = {};
    float lacc[2][4] = {};
    const uint32_t ONES = 0x3C003C00u;

    const int NT = NSP / KB;   // 32 tiles
    for (int t = 0; t < NT; ++t) {
        const int b = t & 1;
        sts_V(b);
        CP_WAIT0();
        __syncthreads();
        if (t + 1 < NT) { cp_K(b ^ 1, (t + 1) * KB); ldg_V((t + 1) * KB); }

        // fused per 16-key chunk: QK MMA -> ex2 -> pack (reg P) -> l-MMA + PV MMA
        #pragma unroll
        for (int kc = 0; kc < 8; ++kc) {
            float s[2][2][4] = {};    // [u][ntp][4]
            #pragma unroll
            for (int ks = 0; ks < 2; ++ks) {
                #pragma unroll
                for (int ntp = 0; ntp < 2; ++ntp) {
                    uint32_t b0 = Ksm[b][ks * 8 + tig][kc * 16 + ntp * 8 + gid];
                    uint32_t b1 = Ksm[b][ks * 8 + tig + 4][kc * 16 + ntp * 8 + gid];
                    mmaf16(s[0][ntp], qa[0][ks], b0, b1);
                    mmaf16(s[1][ntp], qa[1][ks], b0, b1);
                }
            }
            uint32_t aP[2][4];
            #pragma unroll
            for (int u = 0; u < 2; ++u) {
                aP[u][0] = packh2(ex2(s[u][0][0]), ex2(s[u][0][1]));
                aP[u][1] = packh2(ex2(s[u][0][2]), ex2(s[u][0][3]));
                aP[u][2] = packh2(ex2(s[u][1][0]), ex2(s[u][1][1]));
                aP[u][3] = packh2(ex2(s[u][1][2]), ex2(s[u][1][3]));
                mmaf16(lacc[u], aP[u], ONES, ONES);
            }
            #pragma unroll
            for (int nt = 0; nt < 4; ++nt) {
                uint32_t b0 = Vsm[b][nt * 8 + gid][kc * 8 + tig];
                uint32_t b1 = Vsm[b][nt * 8 + gid][kc * 8 + tig + 4];
                mmaf16(o[0][nt], aP[0], b0, b1);
                mmaf16(o[1][nt], aP[1], b0, b1);
            }
        }
    }

    const float il[2][2] = { {1.f / lacc[0][0], 1.f / lacc[0][2]},
                             {1.f / lacc[1][0], 1.f / lacc[1][2]} };

    __syncthreads();
    float* Pf = (float*)(Psm + w * 32 * 36);
    #pragma unroll
    for (int u = 0; u < 2; ++u)
        #pragma unroll
        for (int nt = 0; nt < 4; ++nt) {
            const int c0 = nt * 8 + 2 * tig;
            *(float2*)&Pf[(u * 16 + gid) * 36 + c0] =
                make_float2(o[u][nt][0] * il[u][0], o[u][nt][1] * il[u][0]);
            *(float2*)&Pf[(u * 16 + gid + 8) * 36 + c0] =
                make_float2(o[u][nt][2] * il[u][1], o[u][nt][3] * il[u][1]);
        }
    __syncwarp();

    const float* Pr = Pf + lane * 36;
    uint32_t* ob = out2 + (size_t)(h * 16) * NSP + n0 + w * 32 + lane;
    #pragma unroll
    for (int dp = 0; dp < 16; ++dp) {
        float2 v = *(const float2*)&Pr[2 * dp];
        ob[(size_t)dp * NSP] = packh2(v.x, v.y);
    }
}

// ---------------------------------------------------------------------------
extern "C" void kernel_launch(void* const* d_in, const int* in_sizes, int n_in,
                              void* d_out, int out_size)
{
    const float* x      = (const float*)d_in[0];
    const float* w_dw   = (const float*)d_in[1];
    const float* b_dw   = (const float*)d_in[2];
    const float* w_qkv  = (const float*)d_in[3];
    const float* b_qkv  = (const float*)d_in[4];
    const float* w_proj = (const float*)d_in[5];
    const float* b_proj = (const float*)d_in[6];
    float* outp = (float*)d_out;

    uint32_t *py2, *pqkv2, *patt2;
    cudaGetSymbolAddress((void**)&py2,   g_y2);
    cudaGetSymbolAddress((void**)&pqkv2, g_qkv2);
    cudaGetSymbolAddress((void**)&patt2, g_att2);

    const float SC = 0.17677669529663688f * 1.4426950408889634f; // hd^-0.5 * log2e
    const int GEMM128_SMEM = (2 * 128 * 36 + 2 * 32 * 136) * 4;  // 71680 B
    const int GEMM64_SMEM  = (2 * 128 * 36 + 2 * 32 * 72)  * 4;  // 55296 B
    const int ATTN_SMEM    = (2 * 16 * 136 + 2 * 32 * 68 + 8 * 32 * 36) * 4; // 71680 B
    static int smem_set = 0;
    if (!smem_set) {
        cudaFuncSetAttribute(gemm_h<128, true>, cudaFuncAttributeMaxDynamicSharedMemorySize, GEMM128_SMEM);
        cudaFuncSetAttribute(gemm_h<64, false>, cudaFuncAttributeMaxDynamicSharedMemorySize, GEMM64_SMEM);
        cudaFuncSetAttribute(attn_h,            cudaFuncAttributeMaxDynamicSharedMemorySize, ATTN_SMEM);
        smem_set = 1;
    }

    conv_in_kernel<<<CCH / 2, 256>>>(x, w_dw, b_dw, py2);
    gemm_h<128, true><<<dim3(NSP / 128, (3 * CCH) / 128), 256, GEMM128_SMEM>>>(
        w_qkv, py2, b_qkv, pqkv2, 3 * CCH, NSP, CCH, SC);
    attn_h<<<dim3(NSP / QB, NHEADS), 256, ATTN_SMEM>>>(pqkv2, patt2);
    gemm_h<64, false><<<dim3(NSP / 64, CCH / 128), 256, GEMM64_SMEM>>>(
        w_proj, patt2, b_proj, outp, CCH, NSP, CCH, 1.0f);
}

// round 10
// speedup vs baseline: 2.5082x; 1.0706x over previous
#include <cuda_runtime.h>
#include <cuda_fp16.h>
#include <cstdint>

#define NSP 4096      // H*W*D = 16^3
#define CCH 256
#define NHEADS 8
#define HD 32
#define QB 256
#define KB 128

// scratch, all channel-pair-interleaved half2 words: X2[c/2][n] = half2(X[c],X[c+1])
__device__ uint32_t g_y2[(CCH / 2) * NSP];
__device__ uint32_t g_qkv2[(3 * CCH / 2) * NSP];   // Q rows pre-scaled by hd^-.5*log2e
__device__ uint32_t g_att2[(CCH / 2) * NSP];

// ---------------------------------------------------------------------------
__device__ __forceinline__ uint32_t smem_u32(const void* p) {
    uint32_t a;
    asm("{ .reg .u64 t; cvta.to.shared.u64 t, %1; cvt.u32.u64 %0, t; }" : "=r"(a) : "l"(p));
    return a;
}
__device__ __forceinline__ void cp16(uint32_t saddr, const void* g) {
    asm volatile("cp.async.cg.shared.global [%0], [%1], 16;" :: "r"(saddr), "l"(g));
}
#define CP_COMMIT() asm volatile("cp.async.commit_group;" ::: "memory")
#define CP_WAIT0()  asm volatile("cp.async.wait_group 0;" ::: "memory")

__device__ __forceinline__ void mmaf16(float c[4], const uint32_t a[4],
                                       uint32_t b0, uint32_t b1) {
    asm("mma.sync.aligned.m16n8k16.row.col.f32.f16.f16.f32 "
        "{%0,%1,%2,%3}, {%4,%5,%6,%7}, {%8,%9}, {%0,%1,%2,%3};"
        : "+f"(c[0]), "+f"(c[1]), "+f"(c[2]), "+f"(c[3])
        : "r"(a[0]), "r"(a[1]), "r"(a[2]), "r"(a[3]), "r"(b0), "r"(b1));
}
__device__ __forceinline__ uint32_t packh2(float lo, float hi) {
    __half2 h = __float22half2_rn(make_float2(lo, hi));
    return *reinterpret_cast<uint32_t*>(&h);
}
__device__ __forceinline__ uint32_t ex2h2(uint32_t x) {
    uint32_t r; asm("ex2.approx.f16x2 %0, %1;" : "=r"(r) : "r"(x)); return r;
}
__device__ __forceinline__ uint32_t prmt(uint32_t a, uint32_t b, uint32_t sel) {
    uint32_t d; asm("prmt.b32 %0, %1, %2, %3;" : "=r"(d) : "r"(a), "r"(b), "r"(sel)); return d;
}

// ---------------------------------------------------------------------------
// Kernel 1: depthwise 3x3x3 conv + bias + InstanceNorm; 2 channels/block,
// two sequential passes; output packed half2 pair-interleaved.
// ---------------------------------------------------------------------------
__global__ __launch_bounds__(256) void conv_in_kernel(
    const float* __restrict__ x, const float* __restrict__ wdw,
    const float* __restrict__ bdw, uint32_t* __restrict__ y2)
{
    const int cp  = blockIdx.x;      // channel pair
    const int tid = threadIdx.x;
    __shared__ float xs[NSP];
    __shared__ float red[512];

    const int w  = tid >> 4;
    const int dd = tid & 15;

    float prev[16];
    float out[16];

    for (int s = 0; s < 2; ++s) {
        const int c = 2 * cp + s;
        __syncthreads();
        const float4* xg = (const float4*)(x + (size_t)c * NSP);
        float4* xs4 = (float4*)xs;
        #pragma unroll
        for (int i = 0; i < 4; ++i) xs4[tid + 256 * i] = xg[tid + 256 * i];

        float wr[27];
        #pragma unroll
        for (int i = 0; i < 27; ++i) wr[i] = wdw[c * 27 + i];
        const float bias = bdw[c];
        __syncthreads();

        float sm = 0.f, s2 = 0.f;
        for (int hh = 0; hh < 16; ++hh) {
            float acc = bias;
            #pragma unroll
            for (int i = 0; i < 3; ++i) {
                int ih = hh + i - 1;
                if ((unsigned)ih < 16u) {
                    #pragma unroll
                    for (int j = 0; j < 3; ++j) {
                        int iw = w + j - 1;
                        if ((unsigned)iw < 16u) {
                            #pragma unroll
                            for (int k = 0; k < 3; ++k) {
                                int id = dd + k - 1;
                                if ((unsigned)id < 16u)
                                    acc = fmaf(xs[ih * 256 + iw * 16 + id], wr[i * 9 + j * 3 + k], acc);
                            }
                        }
                    }
                }
            }
            out[hh] = acc;
            sm += acc;
            s2 = fmaf(acc, acc, s2);
        }

        red[tid] = sm; red[256 + tid] = s2;
        __syncthreads();
        for (int st = 128; st > 0; st >>= 1) {
            if (tid < st) { red[tid] += red[tid + st]; red[256 + tid] += red[256 + tid + st]; }
            __syncthreads();
        }
        const float mean = red[0] * (1.0f / NSP);
        const float var  = red[256] * (1.0f / NSP) - mean * mean;
        const float rs   = rsqrtf(var + 1e-5f);

        if (s == 0) {
            for (int hh = 0; hh < 16; ++hh) prev[hh] = (out[hh] - mean) * rs;
        } else {
            for (int hh = 0; hh < 16; ++hh)
                y2[(size_t)cp * NSP + hh * 256 + tid] = packh2(prev[hh], (out[hh] - mean) * rs);
        }
    }
}

// ---------------------------------------------------------------------------
// Kernel 2/4: fp16 mma.sync GEMM, SINGLE-STAGE full K=256 (no k-loop syncs).
// C[M,N] = A[M,K]*B[K,N] + bias[m]. BM=128, 8 warps (4m x 2n).
// B cp.async issued first; A LDG/cvt/STS overlaps it. One __syncthreads,
// then 16 uninterrupted MMA k-steps.
// smem words: As[128][132] + Bs[128][BN+8].
// ---------------------------------------------------------------------------
template<int BN, bool HOUT>
__global__ __launch_bounds__(256) void gemm_h(
    const float* __restrict__ A, const uint32_t* __restrict__ B2,
    const float* __restrict__ bias, void* __restrict__ Cout,
    int M, int N, float qsc)
{
    constexpr int K   = 256;
    constexpr int BSW = BN + 8;
    constexpr int NTW = BN / 16;
    extern __shared__ uint32_t gsm[];
    auto As = (uint32_t(*)[132])gsm;                 // [128][132]
    auto Bs = (uint32_t(*)[BSW])(gsm + 128 * 132);   // [128][BSW]

    const int tid  = threadIdx.x;
    const int w    = tid >> 5;
    const int lane = tid & 31;
    const int gid  = lane >> 2;
    const int tig  = lane & 3;
    const int wm   = w >> 1;
    const int wn   = w & 1;
    const int bm   = blockIdx.y * 128;
    const int bn   = blockIdx.x * BN;

    // B: 128 k-pair rows; 8 threads/row, 4 row-groups per thread
    {
        const int bkp = tid >> 3;
        const int bc  = (tid & 7) * (BN / 8);
        #pragma unroll
        for (int i = 0; i < 4; ++i) {
            const uint32_t* br = B2 + (size_t)(bkp + 32 * i) * N + bn + bc;
            #pragma unroll
            for (int p = 0; p < BN / 32; ++p)
                cp16(smem_u32(&Bs[bkp + 32 * i][bc + p * 4]), br + p * 4);
        }
        CP_COMMIT();
    }
    // A: 2 threads/row, each converts 128 floats -> 64 half2 words
    {
        const int am  = tid >> 1;
        const int akh = tid & 1;
        const float* ar = A + (size_t)(bm + am) * K + akh * 128;
        #pragma unroll
        for (int p = 0; p < 32; ++p) {
            float4 f = *(const float4*)(ar + p * 4);
            As[am][akh * 64 + 2 * p]     = packh2(f.x, f.y);
            As[am][akh * 64 + 2 * p + 1] = packh2(f.z, f.w);
        }
    }
    CP_WAIT0();
    __syncthreads();

    float acc[2][NTW][4] = {};
    #pragma unroll
    for (int ks = 0; ks < 16; ++ks) {
        uint32_t a[2][4];
        #pragma unroll
        for (int u = 0; u < 2; ++u) {
            const int mb = wm * 32 + u * 16 + gid;
            a[u][0] = As[mb][ks * 8 + tig];
            a[u][1] = As[mb + 8][ks * 8 + tig];
            a[u][2] = As[mb][ks * 8 + tig + 4];
            a[u][3] = As[mb + 8][ks * 8 + tig + 4];
        }
        #pragma unroll
        for (int nt = 0; nt < NTW; ++nt) {
            uint32_t b0 = Bs[ks * 8 + tig][wn * (BN / 2) + nt * 8 + gid];
            uint32_t b1 = Bs[ks * 8 + tig + 4][wn * (BN / 2) + nt * 8 + gid];
            mmaf16(acc[0][nt], a[0], b0, b1);
            mmaf16(acc[1][nt], a[1], b0, b1);
        }
    }
    __syncthreads();

    if (HOUT) {
        const float sc = (bm < 256) ? qsc : 1.0f;
        uint32_t* Cs32 = gsm;                    // halves tile, row stride BSW halves
        constexpr int CSW = BSW / 2;
        #pragma unroll
        for (int u = 0; u < 2; ++u) {
            const int r0 = wm * 32 + u * 16 + gid;
            const float bv0 = bias[bm + r0];
            const float bv1 = bias[bm + r0 + 8];
            #pragma unroll
            for (int nt = 0; nt < NTW; ++nt) {
                const int wc = wn * (BN / 4) + nt * 4 + tig;
                Cs32[r0 * CSW + wc]       = packh2((acc[u][nt][0] + bv0) * sc,
                                                   (acc[u][nt][1] + bv0) * sc);
                Cs32[(r0 + 8) * CSW + wc] = packh2((acc[u][nt][2] + bv1) * sc,
                                                   (acc[u][nt][3] + bv1) * sc);
            }
        }
        __syncthreads();
        const unsigned short* Ch = (const unsigned short*)gsm;
        uint32_t* C2 = (uint32_t*)Cout;
        const int n  = tid & (BN - 1);
        const int rg = tid / BN;
        constexpr int RPT = BN / 4;
        #pragma unroll
        for (int p = 0; p < RPT; ++p) {
            const int r = rg * RPT + p;
            uint32_t lo = Ch[(2 * r) * BSW + n];
            uint32_t hi = Ch[(2 * r + 1) * BSW + n];
            C2[(size_t)((bm >> 1) + r) * N + bn + n] = lo | (hi << 16);
        }
    } else {
        float* C = (float*)Cout;
        #pragma unroll
        for (int u = 0; u < 2; ++u) {
            const int m0 = bm + wm * 32 + u * 16 + gid;
            const float bv0 = bias[m0];
            const float bv1 = bias[m0 + 8];
            #pragma unroll
            for (int nt = 0; nt < NTW; ++nt) {
                const int n = bn + wn * (BN / 2) + nt * 8 + tig * 2;
                *(float2*)(C + (size_t)m0 * N + n) =
                    make_float2(acc[u][nt][0] + bv0, acc[u][nt][1] + bv0);
                *(float2*)(C + (size_t)(m0 + 8) * N + n) =
                    make_float2(acc[u][nt][2] + bv1, acc[u][nt][3] + bv1);
            }
        }
    }
}

// ---------------------------------------------------------------------------
// Kernel 3: fp16 flash attention, fully fused per 16-key chunk; P in registers
// (QK C-frag of two adjacent n-tiles == PV A-frag). exp via ex2.approx.f16x2
// (2 exps / MUFU instr). KB=128 keys/tile (32 tiles), QB=256, 8 warps.
// smem words: Ksm[2][16][136] + Vsm[2][32][68] + Psm[8][32][36] (epilogue only).
// ---------------------------------------------------------------------------
__global__ __launch_bounds__(256) void attn_h(
    const uint32_t* __restrict__ qkv2, uint32_t* __restrict__ out2)
{
    extern __shared__ uint32_t dsm[];
    auto Ksm = (uint32_t(*)[16][136])dsm;
    auto Vsm = (uint32_t(*)[32][68])(dsm + 2 * 16 * 136);
    uint32_t* Psm = dsm + 2 * 16 * 136 + 2 * 32 * 68;   // [8][32][36]

    const int tid  = threadIdx.x;
    const int w    = tid >> 5;
    const int lane = tid & 31;
    const int gid  = lane >> 2;
    const int tig  = lane & 3;
    const int h    = blockIdx.y;
    const int n0   = blockIdx.x * QB;

    const uint32_t* Qb = qkv2 + (size_t)(h * 16) * NSP;
    const uint32_t* Kb = qkv2 + (size_t)(128 + h * 16) * NSP;
    const uint32_t* Vb = qkv2 + (size_t)(256 + h * 16) * NSP;

    const int sp = tid >> 4;          // 0..15: K row / V dim-pair
    const int sc = (tid & 15) * 8;    // K col base / V key base

    uint4 vr0, vr1;
    auto ldg_V = [&](int j0) {
        vr0 = *(const uint4*)(Vb + (size_t)sp * NSP + j0 + sc);
        vr1 = *(const uint4*)(Vb + (size_t)sp * NSP + j0 + sc + 4);
    };
    auto sts_V = [&](int b) {
        const int kp = sc >> 1;
        Vsm[b][2 * sp][kp]         = prmt(vr0.x, vr0.y, 0x5410);
        Vsm[b][2 * sp + 1][kp]     = prmt(vr0.x, vr0.y, 0x7632);
        Vsm[b][2 * sp][kp + 1]     = prmt(vr0.z, vr0.w, 0x5410);
        Vsm[b][2 * sp + 1][kp + 1] = prmt(vr0.z, vr0.w, 0x7632);
        Vsm[b][2 * sp][kp + 2]     = prmt(vr1.x, vr1.y, 0x5410);
        Vsm[b][2 * sp + 1][kp + 2] = prmt(vr1.x, vr1.y, 0x7632);
        Vsm[b][2 * sp][kp + 3]     = prmt(vr1.z, vr1.w, 0x5410);
        Vsm[b][2 * sp + 1][kp + 3] = prmt(vr1.z, vr1.w, 0x7632);
    };
    auto cp_K = [&](int b, int j0) {
        const uint32_t* src = Kb + (size_t)sp * NSP + j0 + sc;
        cp16(smem_u32(&Ksm[b][sp][sc]), src);
        cp16(smem_u32(&Ksm[b][sp][sc + 4]), src + 4);
        CP_COMMIT();
    };

    cp_K(0, 0);
    ldg_V(0);

    // Q fragments (pre-scaled half2 dim-pairs)
    uint32_t qa[2][2][4];
    #pragma unroll
    for (int u = 0; u < 2; ++u) {
        const int rl = n0 + w * 32 + u * 16 + gid;
        #pragma unroll
        for (int ks = 0; ks < 2; ++ks) {
            const uint32_t* q0 = Qb + (size_t)(ks * 8 + tig) * NSP + rl;
            const uint32_t* q1 = Qb + (size_t)(ks * 8 + tig + 4) * NSP + rl;
            qa[u][ks][0] = q0[0];
            qa[u][ks][1] = q0[8];
            qa[u][ks][2] = q1[0];
            qa[u][ks][3] = q1[8];
        }
    }

    float o[2][4][4] = {};
    float lacc[2][4] = {};
    const uint32_t ONES = 0x3C003C00u;

    const int NT = NSP / KB;   // 32 tiles
    for (int t = 0; t < NT; ++t) {
        const int b = t & 1;
        sts_V(b);
        CP_WAIT0();
        __syncthreads();
        if (t + 1 < NT) { cp_K(b ^ 1, (t + 1) * KB); ldg_V((t + 1) * KB); }

        // fused per 16-key chunk: QK MMA -> cvt -> ex2.f16x2 (reg P) -> l/PV MMA
        #pragma unroll
        for (int kc = 0; kc < 8; ++kc) {
            float s[2][2][4] = {};    // [u][ntp][4]
            #pragma unroll
            for (int ks = 0; ks < 2; ++ks) {
                #pragma unroll
                for (int ntp = 0; ntp < 2; ++ntp) {
                    uint32_t b0 = Ksm[b][ks * 8 + tig][kc * 16 + ntp * 8 + gid];
                    uint32_t b1 = Ksm[b][ks * 8 + tig + 4][kc * 16 + ntp * 8 + gid];
                    mmaf16(s[0][ntp], qa[0][ks], b0, b1);
                    mmaf16(s[1][ntp], qa[1][ks], b0, b1);
                }
            }
            uint32_t aP[2][4];
            #pragma unroll
            for (int u = 0; u < 2; ++u) {
                aP[u][0] = ex2h2(packh2(s[u][0][0], s[u][0][1]));
                aP[u][1] = ex2h2(packh2(s[u][0][2], s[u][0][3]));
                aP[u][2] = ex2h2(packh2(s[u][1][0], s[u][1][1]));
                aP[u][3] = ex2h2(packh2(s[u][1][2], s[u][1][3]));
                mmaf16(lacc[u], aP[u], ONES, ONES);
            }
            #pragma unroll
            for (int nt = 0; nt < 4; ++nt) {
                uint32_t b0 = Vsm[b][nt * 8 + gid][kc * 8 + tig];
                uint32_t b1 = Vsm[b][nt * 8 + gid][kc * 8 + tig + 4];
                mmaf16(o[0][nt], aP[0], b0, b1);
                mmaf16(o[1][nt], aP[1], b0, b1);
            }
        }
    }

    const float il[2][2] = { {1.f / lacc[0][0], 1.f / lacc[0][2]},
                             {1.f / lacc[1][0], 1.f / lacc[1][2]} };

    __syncthreads();
    float* Pf = (float*)(Psm + w * 32 * 36);
    #pragma unroll
    for (int u = 0; u < 2; ++u)
        #pragma unroll
        for (int nt = 0; nt < 4; ++nt) {
            const int c0 = nt * 8 + 2 * tig;
            *(float2*)&Pf[(u * 16 + gid) * 36 + c0] =
                make_float2(o[u][nt][0] * il[u][0], o[u][nt][1] * il[u][0]);
            *(float2*)&Pf[(u * 16 + gid + 8) * 36 + c0] =
                make_float2(o[u][nt][2] * il[u][1], o[u][nt][3] * il[u][1]);
        }
    __syncwarp();

    const float* Pr = Pf + lane * 36;
    uint32_t* ob = out2 + (size_t)(h * 16) * NSP + n0 + w * 32 + lane;
    #pragma unroll
    for (int dp = 0; dp < 16; ++dp) {
        float2 v = *(const float2*)&Pr[2 * dp];
        ob[(size_t)dp * NSP] = packh2(v.x, v.y);
    }
}

// ---------------------------------------------------------------------------
extern "C" void kernel_launch(void* const* d_in, const int* in_sizes, int n_in,
                              void* d_out, int out_size)
{
    const float* x      = (const float*)d_in[0];
    const float* w_dw   = (const float*)d_in[1];
    const float* b_dw   = (const float*)d_in[2];
    const float* w_qkv  = (const float*)d_in[3];
    const float* b_qkv  = (const float*)d_in[4];
    const float* w_proj = (const float*)d_in[5];
    const float* b_proj = (const float*)d_in[6];
    float* outp = (float*)d_out;

    uint32_t *py2, *pqkv2, *patt2;
    cudaGetSymbolAddress((void**)&py2,   g_y2);
    cudaGetSymbolAddress((void**)&pqkv2, g_qkv2);
    cudaGetSymbolAddress((void**)&patt2, g_att2);

    const float SC = 0.17677669529663688f * 1.4426950408889634f; // hd^-0.5 * log2e
    const int GEMM128_SMEM = (128 * 132 + 128 * 136) * 4;   // 137216 B
    const int GEMM64_SMEM  = (128 * 132 + 128 * 72)  * 4;   // 104448 B
    const int ATTN_SMEM    = (2 * 16 * 136 + 2 * 32 * 68 + 8 * 32 * 36) * 4; // 71680 B
    static int smem_set = 0;
    if (!smem_set) {
        cudaFuncSetAttribute(gemm_h<128, true>, cudaFuncAttributeMaxDynamicSharedMemorySize, GEMM128_SMEM);
        cudaFuncSetAttribute(gemm_h<64, false>, cudaFuncAttributeMaxDynamicSharedMemorySize, GEMM64_SMEM);
        cudaFuncSetAttribute(attn_h,            cudaFuncAttributeMaxDynamicSharedMemorySize, ATTN_SMEM);
        smem_set = 1;
    }

    conv_in_kernel<<<CCH / 2, 256>>>(x, w_dw, b_dw, py2);
    gemm_h<128, true><<<dim3(NSP / 128, (3 * CCH) / 128), 256, GEMM128_SMEM>>>(
        w_qkv, py2, b_qkv, pqkv2, 3 * CCH, NSP, SC);
    attn_h<<<dim3(NSP / QB, NHEADS), 256, ATTN_SMEM>>>(pqkv2, patt2);
    gemm_h<64, false><<<dim3(NSP / 64, CCH / 128), 256, GEMM64_SMEM>>>(
        w_proj, patt2, b_proj, outp, CCH, NSP, 1.0f);
}